// round 1
// baseline (speedup 1.0000x reference)
#include <cuda_runtime.h>
#include <math.h>

#define ROWS  8192          // B*S
#define DM    768
#define DMLP  3072
#define QKVN  2304
#define NHEAD 12
#define DHEAD 64
#define SEQ   1024

// ---- scratch (device globals; no allocation allowed) ----
__device__ float g_xln[ROWS * DM];
__device__ float g_qkvbuf[ROWS * QKVN];
__device__ float g_zbuf[ROWS * DM];
__device__ float g_mid[ROWS * DM];
__device__ float g_hidden[ROWS * DMLP];
__device__ float g_wqkv[DM * QKVN];
__device__ float g_bqkv[QKVN];

__device__ __forceinline__ float gelu_new_f(float x) {
    float x3 = x * x * x;
    float t  = tanhf(0.7978845608028654f * (x + 0.044715f * x3));
    return 0.5f * x * (1.0f + t);
}

// ---------------- pack W_Q/K/V -> [768, 2304], biases -> [2304] ----------------
__global__ void pack_wqkv_kernel(const float* __restrict__ WQ, const float* __restrict__ WK,
                                 const float* __restrict__ WV, const float* __restrict__ bQ,
                                 const float* __restrict__ bK, const float* __restrict__ bV) {
    int idx = blockIdx.x * 256 + threadIdx.x;
    if (idx < DM * QKVN) {
        int d = idx / QKVN;
        int j = idx - d * QKVN;
        int which = j / DM;          // 0=Q 1=K 2=V
        int jj = j - which * DM;
        int h = jj >> 6, e = jj & 63;
        const float* W = (which == 0) ? WQ : (which == 1) ? WK : WV;
        g_wqkv[idx] = W[(h * DM + d) * DHEAD + e];  // W[h, d, e]
    }
    if (idx < QKVN) {
        g_bqkv[idx] = (idx < DM) ? bQ[idx] : (idx < 2 * DM) ? bK[idx - DM] : bV[idx - 2 * DM];
    }
}

// ---------------- LayerNorm: one block (256 thr) per row of 768 ----------------
__global__ void layernorm_kernel(const float* __restrict__ x, const float* __restrict__ w,
                                 const float* __restrict__ b, float* __restrict__ y) {
    int row = blockIdx.x;
    int tid = threadIdx.x;
    const float* xr = x + (size_t)row * DM;
    float v0 = xr[tid], v1 = xr[tid + 256], v2 = xr[tid + 512];
    float s  = v0 + v1 + v2;
    float ss = v0 * v0 + v1 * v1 + v2 * v2;
#pragma unroll
    for (int o = 16; o > 0; o >>= 1) {
        s  += __shfl_xor_sync(0xffffffffu, s, o);
        ss += __shfl_xor_sync(0xffffffffu, ss, o);
    }
    __shared__ float shs[8], shss[8];
    int warp = tid >> 5, lane = tid & 31;
    if (lane == 0) { shs[warp] = s; shss[warp] = ss; }
    __syncthreads();
    if (tid < 32) {
        s  = (lane < 8) ? shs[lane] : 0.f;
        ss = (lane < 8) ? shss[lane] : 0.f;
#pragma unroll
        for (int o = 4; o > 0; o >>= 1) {
            s  += __shfl_xor_sync(0xffffffffu, s, o);
            ss += __shfl_xor_sync(0xffffffffu, ss, o);
        }
        if (lane == 0) { shs[0] = s; shss[0] = ss; }
    }
    __syncthreads();
    s = shs[0]; ss = shss[0];
    float mean = s * (1.f / DM);
    float var  = ss * (1.f / DM) - mean * mean;
    float rstd = rsqrtf(var + 1e-5f);
    float* yr = y + (size_t)row * DM;
    yr[tid]       = (v0 - mean) * rstd * w[tid]       + b[tid];
    yr[tid + 256] = (v1 - mean) * rstd * w[tid + 256] + b[tid + 256];
    yr[tid + 512] = (v2 - mean) * rstd * w[tid + 512] + b[tid + 512];
}

// ---------------- SGEMM 128x128x8, 256 threads, 8x8 per thread ----------------
// EPI: 0 = +bias, 1 = +bias then GELU, 2 = +bias +residual R
template <int EPI>
__global__ __launch_bounds__(256, 2) void sgemm_kernel(
    const float* __restrict__ A, const float* __restrict__ B,
    const float* __restrict__ bias, const float* __restrict__ R,
    float* __restrict__ C, int M, int N, int K) {
    __shared__ float As[2][8][128];
    __shared__ float Bs[2][8][128];
    int tid = threadIdx.x;
    int bx = blockIdx.x, by = blockIdx.y;
    const float* Ab = A + (size_t)by * 128 * K;
    const float* Bb = B + (size_t)bx * 128;
    int arow = tid >> 1;
    int acol = (tid & 1) << 2;
    int brow = tid >> 5;
    int bcol = (tid & 31) << 2;
    int tx = tid & 15, ty = tid >> 4;

    float c[8][8];
#pragma unroll
    for (int i = 0; i < 8; i++)
#pragma unroll
        for (int j = 0; j < 8; j++) c[i][j] = 0.f;

    float4 av = *(const float4*)(Ab + (size_t)arow * K + acol);
    float4 bv = *(const float4*)(Bb + (size_t)brow * N + bcol);
    As[0][acol + 0][arow] = av.x; As[0][acol + 1][arow] = av.y;
    As[0][acol + 2][arow] = av.z; As[0][acol + 3][arow] = av.w;
    *(float4*)&Bs[0][brow][bcol] = bv;
    __syncthreads();

    int nk = K >> 3;
    for (int kt = 0; kt < nk; kt++) {
        int cur = kt & 1;
        if (kt + 1 < nk) {
            av = *(const float4*)(Ab + (size_t)arow * K + (kt + 1) * 8 + acol);
            bv = *(const float4*)(Bb + (size_t)((kt + 1) * 8 + brow) * N + bcol);
        }
#pragma unroll
        for (int k = 0; k < 8; k++) {
            float a[8], bf[8];
            *(float4*)(a)      = *(const float4*)&As[cur][k][ty * 4];
            *(float4*)(a + 4)  = *(const float4*)&As[cur][k][64 + ty * 4];
            *(float4*)(bf)     = *(const float4*)&Bs[cur][k][tx * 4];
            *(float4*)(bf + 4) = *(const float4*)&Bs[cur][k][64 + tx * 4];
#pragma unroll
            for (int i = 0; i < 8; i++)
#pragma unroll
                for (int j = 0; j < 8; j++)
                    c[i][j] = fmaf(a[i], bf[j], c[i][j]);
        }
        if (kt + 1 < nk) {
            int nxt = cur ^ 1;
            As[nxt][acol + 0][arow] = av.x; As[nxt][acol + 1][arow] = av.y;
            As[nxt][acol + 2][arow] = av.z; As[nxt][acol + 3][arow] = av.w;
            *(float4*)&Bs[nxt][brow][bcol] = bv;
        }
        __syncthreads();
    }

    int row0 = by * 128, col0 = bx * 128;
#pragma unroll
    for (int i = 0; i < 8; i++) {
        int r = row0 + ((i < 4) ? (ty * 4 + i) : (64 + ty * 4 + i - 4));
#pragma unroll
        for (int jh = 0; jh < 2; jh++) {
            int col = col0 + jh * 64 + tx * 4;
            float4 v;
            v.x = c[i][jh * 4 + 0]; v.y = c[i][jh * 4 + 1];
            v.z = c[i][jh * 4 + 2]; v.w = c[i][jh * 4 + 3];
            float4 bb = *(const float4*)(bias + col);
            v.x += bb.x; v.y += bb.y; v.z += bb.z; v.w += bb.w;
            if (EPI == 1) {
                v.x = gelu_new_f(v.x); v.y = gelu_new_f(v.y);
                v.z = gelu_new_f(v.z); v.w = gelu_new_f(v.w);
            }
            if (EPI == 2) {
                float4 rr = *(const float4*)(R + (size_t)r * N + col);
                v.x += rr.x; v.y += rr.y; v.z += rr.z; v.w += rr.w;
            }
            *(float4*)(C + (size_t)r * N + col) = v;
        }
    }
}

// ---------------- causal flash attention, fp32 ----------------
// grid = (8 q-tiles of 128 rows, 96 batch*head). 1 thread = 1 query row.
// q (prescaled) and o live in registers; K/V staged in 64x64 smem tiles.
// Online softmax with lazy rescale: o[] rescaled only on a new running max
// (expected ~ln(n) ~= 7.5 times per row) -> per-key cost is dot + exp + axpy.
__global__ __launch_bounds__(128) void attn_kernel(const float* __restrict__ qkv,
                                                   float* __restrict__ z) {
    __shared__ float Ks[64][64];
    __shared__ float Vs[64][64];
    int qt = blockIdx.x;
    int bh = blockIdx.y;
    int b = bh / NHEAD, h = bh - b * NHEAD;
    int tid = threadIdx.x;
    int qrow = qt * 128 + tid;

    const float4* qp = (const float4*)(qkv + ((size_t)(b * SEQ + qrow)) * QKVN + h * DHEAD);
    float4 q[16];
#pragma unroll
    for (int i = 0; i < 16; i++) {
        float4 t = qp[i];
        t.x *= 0.125f; t.y *= 0.125f; t.z *= 0.125f; t.w *= 0.125f;  // 1/sqrt(64)
        q[i] = t;
    }
    float o[64];
#pragma unroll
    for (int e = 0; e < 64; e++) o[e] = 0.f;
    float m = -INFINITY, l = 0.f;

    size_t kvbase = (size_t)b * SEQ * QKVN + h * DHEAD + DM;  // K block of packed row
    int ntile = 2 * qt + 2;                                    // 64-row tiles covering causal span
    for (int jt = 0; jt < ntile; jt++) {
        __syncthreads();
        for (int i = tid; i < 64 * 16; i += 128) {
            int r = i >> 4, c4 = (i & 15) << 2;
            const float* src = qkv + kvbase + (size_t)(jt * 64 + r) * QKVN + c4;
            *(float4*)&Ks[r][c4] = *(const float4*)src;
            *(float4*)&Vs[r][c4] = *(const float4*)(src + DM);  // V is +768 past K
        }
        __syncthreads();
        int jmax = min(64, qrow - jt * 64 + 1);
        for (int j = 0; j < jmax; j++) {
            const float4* kr = (const float4*)Ks[j];
            float s = 0.f;
#pragma unroll
            for (int i = 0; i < 16; i++) {
                float4 k4 = kr[i];
                s = fmaf(q[i].x, k4.x, s);
                s = fmaf(q[i].y, k4.y, s);
                s = fmaf(q[i].z, k4.z, s);
                s = fmaf(q[i].w, k4.w, s);
            }
            float p;
            if (s > m) {
                float corr = __expf(m - s);   // first key: exp(-inf) = 0
                l *= corr;
#pragma unroll
                for (int e = 0; e < 64; e++) o[e] *= corr;
                m = s;
                p = 1.f;
            } else {
                p = __expf(s - m);
            }
            l += p;
            const float4* vr = (const float4*)Vs[j];
#pragma unroll
            for (int i = 0; i < 16; i++) {
                float4 vv = vr[i];
                o[i * 4 + 0] = fmaf(p, vv.x, o[i * 4 + 0]);
                o[i * 4 + 1] = fmaf(p, vv.y, o[i * 4 + 1]);
                o[i * 4 + 2] = fmaf(p, vv.z, o[i * 4 + 2]);
                o[i * 4 + 3] = fmaf(p, vv.w, o[i * 4 + 3]);
            }
        }
    }
    float inv = 1.f / l;
    float4* zp = (float4*)(z + ((size_t)(b * SEQ + qrow)) * DM + h * DHEAD);
#pragma unroll
    for (int i = 0; i < 16; i++) {
        float4 v;
        v.x = o[i * 4 + 0] * inv; v.y = o[i * 4 + 1] * inv;
        v.z = o[i * 4 + 2] * inv; v.w = o[i * 4 + 3] * inv;
        zp[i] = v;
    }
}

// ---------------- launch ----------------
extern "C" void kernel_launch(void* const* d_in, const int* in_sizes, int n_in,
                              void* d_out, int out_size) {
    const float* resid_pre = (const float*)d_in[0];
    const float* W_Q  = (const float*)d_in[1];
    const float* W_K  = (const float*)d_in[2];
    const float* W_V  = (const float*)d_in[3];
    const float* W_O  = (const float*)d_in[4];
    const float* b_Q  = (const float*)d_in[5];
    const float* b_K  = (const float*)d_in[6];
    const float* b_V  = (const float*)d_in[7];
    const float* b_O  = (const float*)d_in[8];
    const float* ln1w = (const float*)d_in[9];
    const float* ln1b = (const float*)d_in[10];
    const float* ln2w = (const float*)d_in[11];
    const float* ln2b = (const float*)d_in[12];
    const float* W_in  = (const float*)d_in[13];
    const float* b_in  = (const float*)d_in[14];
    const float* W_out = (const float*)d_in[15];
    const float* b_out = (const float*)d_in[16];
    float* out = (float*)d_out;

    float *xln, *qkv, *z, *mid, *hidden, *wqkv, *bqkv;
    cudaGetSymbolAddress((void**)&xln,    g_xln);
    cudaGetSymbolAddress((void**)&qkv,    g_qkvbuf);
    cudaGetSymbolAddress((void**)&z,      g_zbuf);
    cudaGetSymbolAddress((void**)&mid,    g_mid);
    cudaGetSymbolAddress((void**)&hidden, g_hidden);
    cudaGetSymbolAddress((void**)&wqkv,   g_wqkv);
    cudaGetSymbolAddress((void**)&bqkv,   g_bqkv);

    // 1) pack fused QKV weight/bias
    pack_wqkv_kernel<<<(DM * QKVN + 255) / 256, 256>>>(W_Q, W_K, W_V, b_Q, b_K, b_V);
    // 2) LN1
    layernorm_kernel<<<ROWS, 256>>>(resid_pre, ln1w, ln1b, xln);
    // 3) fused QKV projection: [8192,768] x [768,2304]
    sgemm_kernel<0><<<dim3(QKVN / 128, ROWS / 128), 256>>>(xln, wqkv, bqkv, nullptr, qkv,
                                                           ROWS, QKVN, DM);
    // 4) causal attention
    attn_kernel<<<dim3(SEQ / 128, 8 * NHEAD), 128>>>(qkv, z);
    // 5) O projection + bias + residual(resid_pre) -> resid_mid
    sgemm_kernel<2><<<dim3(DM / 128, ROWS / 128), 256>>>(z, W_O, b_O, resid_pre, mid,
                                                         ROWS, DM, DM);
    // 6) LN2
    layernorm_kernel<<<ROWS, 256>>>(mid, ln2w, ln2b, xln);
    // 7) MLP in + bias + GELU
    sgemm_kernel<1><<<dim3(DMLP / 128, ROWS / 128), 256>>>(xln, W_in, b_in, nullptr, hidden,
                                                           ROWS, DMLP, DM);
    // 8) MLP out + bias + residual(resid_mid) -> output
    sgemm_kernel<2><<<dim3(DM / 128, ROWS / 128), 256>>>(hidden, W_out, b_out, mid, out,
                                                         ROWS, DM, DMLP);
}

// round 4
// speedup vs baseline: 2.0900x; 2.0900x over previous
#include <cuda_runtime.h>
#include <cuda_bf16.h>
#include <math.h>
#include <stdint.h>

#define ROWS  8192          // B*S
#define DM    768
#define DMLP  3072
#define QKVN  2304
#define NHEAD 12
#define DHEAD 64
#define SEQ   1024

// ---------------- scratch (device globals; no allocation allowed) ----------------
__device__ float g_xln[ROWS * DM];
__device__ float g_qkvbuf[ROWS * QKVN];
__device__ float g_z[ROWS * DM];
__device__ float g_mid[ROWS * DM];
__device__ float g_hidden[ROWS * DMLP];
__device__ float g_wqkv[QKVN * DM];   // [N=2304][K=768] tf32-rounded
__device__ float g_wo[DM * DM];       // [N=768][K=768]
__device__ float g_win[DMLP * DM];    // [N=3072][K=768]
__device__ float g_wout[DM * DMLP];   // [N=768][K=3072]
__device__ float g_bqkv[QKVN];

// ---------------- helpers ----------------
__device__ __forceinline__ uint32_t smem_to_u32(const void* p) {
    uint32_t a;
    asm("{ .reg .u64 t; cvta.to.shared.u64 t, %1; cvt.u32.u64 %0, t; }" : "=r"(a) : "l"(p));
    return a;
}
__device__ __forceinline__ void cp_async16(uint32_t dst, const void* src) {
    asm volatile("cp.async.cg.shared.global [%0], [%1], 16;\n" :: "r"(dst), "l"(src));
}
#define CP_COMMIT() asm volatile("cp.async.commit_group;\n" ::: "memory")
#define CP_WAIT(n)  asm volatile("cp.async.wait_group %0;\n" :: "n"(n) : "memory")

__device__ __forceinline__ void ldsm_x4(uint32_t& r0, uint32_t& r1, uint32_t& r2, uint32_t& r3,
                                        uint32_t addr) {
    asm volatile("ldmatrix.sync.aligned.m8n8.x4.shared.b16 {%0,%1,%2,%3}, [%4];"
                 : "=r"(r0), "=r"(r1), "=r"(r2), "=r"(r3) : "r"(addr));
}
__device__ __forceinline__ void mma_tf32(float* c, const uint32_t* a, uint32_t b0, uint32_t b1) {
    asm volatile(
        "mma.sync.aligned.m16n8k8.row.col.f32.tf32.tf32.f32 "
        "{%0,%1,%2,%3}, {%4,%5,%6,%7}, {%8,%9}, {%0,%1,%2,%3};"
        : "+f"(c[0]), "+f"(c[1]), "+f"(c[2]), "+f"(c[3])
        : "r"(a[0]), "r"(a[1]), "r"(a[2]), "r"(a[3]), "r"(b0), "r"(b1));
}
// round-to-nearest tf32 (zero-mean error; avoids coherent truncation bias)
__device__ __forceinline__ float to_tf32(float x) {
    uint32_t u;
    asm("cvt.rna.tf32.f32 %0, %1;" : "=r"(u) : "f"(x));
    return __uint_as_float(u);
}

__device__ __forceinline__ float gelu_new_f(float x) {
    float x3 = x * x * x;
    float t  = tanhf(0.7978845608028654f * (x + 0.044715f * x3));
    return 0.5f * x * (1.0f + t);
}

// ---------------- weight packing ----------------
__global__ void pack_wqkv_kernel(const float* __restrict__ WQ, const float* __restrict__ WK,
                                 const float* __restrict__ WV, const float* __restrict__ bQ,
                                 const float* __restrict__ bK, const float* __restrict__ bV) {
    int idx = blockIdx.x * 256 + threadIdx.x;
    if (idx < QKVN * DM) {
        int j = idx / DM;
        int d = idx - j * DM;
        int which = j / DM;
        int jj = j - which * DM;
        int h = jj >> 6, e = jj & 63;
        const float* W = (which == 0) ? WQ : (which == 1) ? WK : WV;
        g_wqkv[idx] = to_tf32(W[(h * DM + d) * DHEAD + e]);
    }
    if (idx < QKVN) {
        g_bqkv[idx] = (idx < DM) ? bQ[idx] : (idx < 2 * DM) ? bK[idx - DM] : bV[idx - 2 * DM];
    }
}

// in[R][C] fp32 -> out[C][R] tf32-rounded fp32   (R, C multiples of 32)
__global__ void transpose_pack_kernel(const float* __restrict__ in,
                                      float* __restrict__ out, int R, int C) {
    __shared__ float t[32][33];
    int bx = blockIdx.x * 32, by = blockIdx.y * 32;
    int x = threadIdx.x, y = threadIdx.y;
#pragma unroll
    for (int i = 0; i < 32; i += 8)
        t[y + i][x] = in[(size_t)(by + y + i) * C + bx + x];
    __syncthreads();
#pragma unroll
    for (int i = 0; i < 32; i += 8)
        out[(size_t)(bx + y + i) * R + by + x] = to_tf32(t[x][y + i]);
}

// ---------------- LayerNorm (emits tf32-rounded fp32) ----------------
__global__ void layernorm_kernel(const float* __restrict__ x, const float* __restrict__ w,
                                 const float* __restrict__ b, float* __restrict__ y) {
    int row = blockIdx.x;
    int tid = threadIdx.x;
    const float* xr = x + (size_t)row * DM;
    float v0 = xr[tid], v1 = xr[tid + 256], v2 = xr[tid + 512];
    float s  = v0 + v1 + v2;
    float ss = v0 * v0 + v1 * v1 + v2 * v2;
#pragma unroll
    for (int o = 16; o > 0; o >>= 1) {
        s  += __shfl_xor_sync(0xffffffffu, s, o);
        ss += __shfl_xor_sync(0xffffffffu, ss, o);
    }
    __shared__ float shs[8], shss[8];
    int warp = tid >> 5, lane = tid & 31;
    if (lane == 0) { shs[warp] = s; shss[warp] = ss; }
    __syncthreads();
    if (tid < 32) {
        s  = (lane < 8) ? shs[lane] : 0.f;
        ss = (lane < 8) ? shss[lane] : 0.f;
#pragma unroll
        for (int o = 4; o > 0; o >>= 1) {
            s  += __shfl_xor_sync(0xffffffffu, s, o);
            ss += __shfl_xor_sync(0xffffffffu, ss, o);
        }
        if (lane == 0) { shs[0] = s; shss[0] = ss; }
    }
    __syncthreads();
    s = shs[0]; ss = shss[0];
    float mean = s * (1.f / DM);
    float var  = ss * (1.f / DM) - mean * mean;
    float rstd = rsqrtf(var + 1e-5f);
    float* yr = y + (size_t)row * DM;
    yr[tid]       = to_tf32((v0 - mean) * rstd * w[tid]       + b[tid]);
    yr[tid + 256] = to_tf32((v1 - mean) * rstd * w[tid + 256] + b[tid + 256]);
    yr[tid + 512] = to_tf32((v2 - mean) * rstd * w[tid + 512] + b[tid + 512]);
}

// ---------------- tf32 HMMA GEMM: C[M,N] = A[M,K] x B[N,K]^T ----------------
// 128x128 CTA tile, 256 threads, warp tile 64x32 via mma.m16n8k8.tf32.
// K staged 32 per stage (128B rows of 32 fp32, XOR-swizzled), 3-stage cp.async.
// Fragments loaded via ldmatrix.b16 viewing 8x4-fp32 segments (lane l -> (l/4, l%4)).
// EPI: 0 = fp32 out +bias;  1 = fp32 out +bias+GELU, tf32-rounded;  2 = +bias+residual
#define STG_BYTES 32768   // A 16KB + B 16KB per stage
template <int EPI>
__global__ __launch_bounds__(256, 1) void gemm_mma_kernel(
    const float* __restrict__ A, const float* __restrict__ B,
    const float* __restrict__ bias, const float* __restrict__ Rres,
    float* __restrict__ Cout, int N, int K) {
    extern __shared__ char smem[];
    int tid = threadIdx.x, lane = tid & 31, wid = tid >> 5;
    int bx = blockIdx.x, by = blockIdx.y;
    int warp_m = (wid & 1) * 64;
    int warp_n = (wid >> 1) * 32;

    const float* Ab = A + (size_t)(by * 128) * K;
    const float* Bb = B + (size_t)(bx * 128) * K;
    uint32_t sbase = smem_to_u32(smem);

    float c[4][4][4];
#pragma unroll
    for (int i = 0; i < 4; i++)
#pragma unroll
        for (int j = 0; j < 4; j++)
#pragma unroll
            for (int k = 0; k < 4; k++) c[i][j][k] = 0.f;

    int T = K >> 5;   // K per stage = 32

    auto load_stage = [&](int s, int kt) {
        uint32_t dstA = sbase + s * STG_BYTES;
        uint32_t dstB = dstA + 16384;
        const float* Ag = Ab + kt * 32;
        const float* Bg = Bb + kt * 32;
#pragma unroll
        for (int i = 0; i < 4; i++) {
            int idx = tid + i * 256;
            int r = idx >> 3, cc = idx & 7;
            uint32_t off = (uint32_t)(r * 128 + ((cc ^ (r & 7)) * 16));
            cp_async16(dstA + off, Ag + (size_t)r * K + cc * 4);
            cp_async16(dstB + off, Bg + (size_t)r * K + cc * 4);
        }
        CP_COMMIT();
    };

    load_stage(0, 0);
    load_stage(1, 1);

    int l7 = lane & 7;
    int lg = lane >> 3;          // 0..3 ldmatrix address group

    for (int t = 0; t < T; t++) {
        if (t + 2 < T) load_stage((t + 2) % 3, t + 2);
        if (t + 2 < T)      { CP_WAIT(2); }
        else if (t + 1 < T) { CP_WAIT(1); }
        else                { CP_WAIT(0); }
        __syncthreads();

        uint32_t sA = sbase + (t % 3) * STG_BYTES;
        uint32_t sB = sA + 16384;
#pragma unroll
        for (int ks = 0; ks < 4; ks++) {
            // A fragments: per m16 tile, x4 -> {rows0-7 k0-3, rows8-15 k0-3,
            //                                   rows0-7 k4-7, rows8-15 k4-7}
            uint32_t a[4][4];
#pragma unroll
            for (int i = 0; i < 4; i++) {
                int row = warp_m + i * 16 + ((lg & 1) << 3) + l7;
                int chunk = ks * 2 + (lg >> 1);
                uint32_t addr = sA + row * 128 + ((chunk ^ (row & 7)) << 4);
                ldsm_x4(a[i][0], a[i][1], a[i][2], a[i][3], addr);
            }
            // B fragments: per x4, two n8 tiles -> {t0.b0, t0.b1, t1.b0, t1.b1}
            uint32_t b[2][4];
#pragma unroll
            for (int j = 0; j < 2; j++) {
                int row = warp_n + (j * 2 + (lg >> 1)) * 8 + l7;
                int chunk = ks * 2 + (lg & 1);
                uint32_t addr = sB + row * 128 + ((chunk ^ (row & 7)) << 4);
                ldsm_x4(b[j][0], b[j][1], b[j][2], b[j][3], addr);
            }
#pragma unroll
            for (int i = 0; i < 4; i++)
#pragma unroll
                for (int jn = 0; jn < 4; jn++)
                    mma_tf32(c[i][jn], a[i], b[jn >> 1][(jn & 1) * 2],
                             b[jn >> 1][(jn & 1) * 2 + 1]);
        }
        __syncthreads();
    }

    // ---- epilogue: direct gmem stores ----
    int quad = lane >> 2, tc2 = (lane & 3) * 2;
#pragma unroll
    for (int i = 0; i < 4; i++) {
#pragma unroll
        for (int jj = 0; jj < 4; jj++) {
            int row0 = by * 128 + warp_m + i * 16 + quad;
            int col  = bx * 128 + warp_n + jj * 8 + tc2;
            float bb0 = bias[col], bb1 = bias[col + 1];
            float v0 = c[i][jj][0] + bb0, v1 = c[i][jj][1] + bb1;
            float v2 = c[i][jj][2] + bb0, v3 = c[i][jj][3] + bb1;
            if (EPI == 1) {
                v0 = to_tf32(gelu_new_f(v0)); v1 = to_tf32(gelu_new_f(v1));
                v2 = to_tf32(gelu_new_f(v2)); v3 = to_tf32(gelu_new_f(v3));
            }
            if (EPI == 2) {
                const float2 r0 = *(const float2*)(Rres + (size_t)row0 * N + col);
                const float2 r1 = *(const float2*)(Rres + (size_t)(row0 + 8) * N + col);
                v0 += r0.x; v1 += r0.y; v2 += r1.x; v3 += r1.y;
            }
            *(float2*)(Cout + (size_t)row0 * N + col)       = make_float2(v0, v1);
            *(float2*)(Cout + (size_t)(row0 + 8) * N + col) = make_float2(v2, v3);
        }
    }
}

// ---------------- causal flash attention, fp32, tf32-rounded z ----------------
__global__ __launch_bounds__(128) void attn_kernel(const float* __restrict__ qkv,
                                                   float* __restrict__ z) {
    __shared__ float Ks[64][64];
    __shared__ float Vs[64][64];
    int qt = blockIdx.x;
    int bh = blockIdx.y;
    int b = bh / NHEAD, h = bh - b * NHEAD;
    int tid = threadIdx.x;
    int qrow = qt * 128 + tid;

    const float4* qp = (const float4*)(qkv + ((size_t)(b * SEQ + qrow)) * QKVN + h * DHEAD);
    float4 q[16];
#pragma unroll
    for (int i = 0; i < 16; i++) {
        float4 t = qp[i];
        t.x *= 0.125f; t.y *= 0.125f; t.z *= 0.125f; t.w *= 0.125f;
        q[i] = t;
    }
    float o[64];
#pragma unroll
    for (int e = 0; e < 64; e++) o[e] = 0.f;
    float m = -INFINITY, l = 0.f;

    size_t kvbase = (size_t)b * SEQ * QKVN + h * DHEAD + DM;
    int ntile = 2 * qt + 2;
    for (int jt = 0; jt < ntile; jt++) {
        __syncthreads();
        for (int i = tid; i < 64 * 16; i += 128) {
            int r = i >> 4, c4 = (i & 15) << 2;
            const float* src = qkv + kvbase + (size_t)(jt * 64 + r) * QKVN + c4;
            *(float4*)&Ks[r][c4] = *(const float4*)src;
            *(float4*)&Vs[r][c4] = *(const float4*)(src + DM);
        }
        __syncthreads();
        int jmax = min(64, qrow - jt * 64 + 1);
        for (int j = 0; j < jmax; j++) {
            const float4* kr = (const float4*)Ks[j];
            float s = 0.f;
#pragma unroll
            for (int i = 0; i < 16; i++) {
                float4 k4 = kr[i];
                s = fmaf(q[i].x, k4.x, s);
                s = fmaf(q[i].y, k4.y, s);
                s = fmaf(q[i].z, k4.z, s);
                s = fmaf(q[i].w, k4.w, s);
            }
            float p;
            if (s > m) {
                float corr = __expf(m - s);
                l *= corr;
#pragma unroll
                for (int e = 0; e < 64; e++) o[e] *= corr;
                m = s;
                p = 1.f;
            } else {
                p = __expf(s - m);
            }
            l += p;
            const float4* vr = (const float4*)Vs[j];
#pragma unroll
            for (int i = 0; i < 16; i++) {
                float4 vv = vr[i];
                o[i * 4 + 0] = fmaf(p, vv.x, o[i * 4 + 0]);
                o[i * 4 + 1] = fmaf(p, vv.y, o[i * 4 + 1]);
                o[i * 4 + 2] = fmaf(p, vv.z, o[i * 4 + 2]);
                o[i * 4 + 3] = fmaf(p, vv.w, o[i * 4 + 3]);
            }
        }
    }
    float inv = 1.f / l;
    float4* zp = (float4*)(z + ((size_t)(b * SEQ + qrow)) * DM + h * DHEAD);
#pragma unroll
    for (int i = 0; i < 16; i++) {
        float4 v;
        v.x = to_tf32(o[i * 4 + 0] * inv); v.y = to_tf32(o[i * 4 + 1] * inv);
        v.z = to_tf32(o[i * 4 + 2] * inv); v.w = to_tf32(o[i * 4 + 3] * inv);
        zp[i] = v;
    }
}

// ---------------- launch ----------------
extern "C" void kernel_launch(void* const* d_in, const int* in_sizes, int n_in,
                              void* d_out, int out_size) {
    const float* resid_pre = (const float*)d_in[0];
    const float* W_Q  = (const float*)d_in[1];
    const float* W_K  = (const float*)d_in[2];
    const float* W_V  = (const float*)d_in[3];
    const float* W_O  = (const float*)d_in[4];
    const float* b_Q  = (const float*)d_in[5];
    const float* b_K  = (const float*)d_in[6];
    const float* b_V  = (const float*)d_in[7];
    const float* b_O  = (const float*)d_in[8];
    const float* ln1w = (const float*)d_in[9];
    const float* ln1b = (const float*)d_in[10];
    const float* ln2w = (const float*)d_in[11];
    const float* ln2b = (const float*)d_in[12];
    const float* W_in  = (const float*)d_in[13];
    const float* b_in  = (const float*)d_in[14];
    const float* W_out = (const float*)d_in[15];
    const float* b_out = (const float*)d_in[16];
    float* out = (float*)d_out;

    float *xln, *qkv, *z, *mid, *hidden, *wqkv, *wo, *win, *wout, *bqkv;
    cudaGetSymbolAddress((void**)&xln,    g_xln);
    cudaGetSymbolAddress((void**)&qkv,    g_qkvbuf);
    cudaGetSymbolAddress((void**)&z,      g_z);
    cudaGetSymbolAddress((void**)&mid,    g_mid);
    cudaGetSymbolAddress((void**)&hidden, g_hidden);
    cudaGetSymbolAddress((void**)&wqkv,   g_wqkv);
    cudaGetSymbolAddress((void**)&wo,     g_wo);
    cudaGetSymbolAddress((void**)&win,    g_win);
    cudaGetSymbolAddress((void**)&wout,   g_wout);
    cudaGetSymbolAddress((void**)&bqkv,   g_bqkv);

    const int SMEM = 3 * STG_BYTES;  // 96KB: 3-stage pipeline
    cudaFuncSetAttribute(gemm_mma_kernel<0>, cudaFuncAttributeMaxDynamicSharedMemorySize, SMEM);
    cudaFuncSetAttribute(gemm_mma_kernel<1>, cudaFuncAttributeMaxDynamicSharedMemorySize, SMEM);
    cudaFuncSetAttribute(gemm_mma_kernel<2>, cudaFuncAttributeMaxDynamicSharedMemorySize, SMEM);

    // weight packing (tf32-rounded fp32, [N,K] layouts)
    pack_wqkv_kernel<<<(QKVN * DM + 255) / 256, 256>>>(W_Q, W_K, W_V, b_Q, b_K, b_V);
    transpose_pack_kernel<<<dim3(DM / 32, DM / 32),   dim3(32, 8)>>>(W_O,  wo,   DM,   DM);
    transpose_pack_kernel<<<dim3(DMLP / 32, DM / 32), dim3(32, 8)>>>(W_in, win,  DM,   DMLP);
    transpose_pack_kernel<<<dim3(DM / 32, DMLP / 32), dim3(32, 8)>>>(W_out, wout, DMLP, DM);

    // 1) LN1 (tf32-rounded out)
    layernorm_kernel<<<ROWS, 256>>>(resid_pre, ln1w, ln1b, xln);
    // 2) fused QKV projection (fp32 out)
    gemm_mma_kernel<0><<<dim3(QKVN / 128, ROWS / 128), 256, SMEM>>>(xln, wqkv, bqkv, nullptr,
                                                                    qkv, QKVN, DM);
    // 3) causal attention (tf32-rounded z)
    attn_kernel<<<dim3(SEQ / 128, 8 * NHEAD), 128>>>(qkv, z);
    // 4) O projection + bias + residual -> mid (fp32)
    gemm_mma_kernel<2><<<dim3(DM / 128, ROWS / 128), 256, SMEM>>>(z, wo, b_O, resid_pre,
                                                                  mid, DM, DM);
    // 5) LN2 (tf32-rounded out)
    layernorm_kernel<<<ROWS, 256>>>(mid, ln2w, ln2b, xln);
    // 6) MLP in + bias + GELU (tf32-rounded out)
    gemm_mma_kernel<1><<<dim3(DMLP / 128, ROWS / 128), 256, SMEM>>>(xln, win, b_in, nullptr,
                                                                    hidden, DMLP, DM);
    // 7) MLP out + bias + residual -> out (fp32)
    gemm_mma_kernel<2><<<dim3(DM / 128, ROWS / 128), 256, SMEM>>>(hidden, wout, b_out, mid,
                                                                  out, DM, DMLP);
}

// round 5
// speedup vs baseline: 3.6906x; 1.7658x over previous
#include <cuda_runtime.h>
#include <cuda_bf16.h>
#include <math.h>
#include <stdint.h>

#define ROWS  8192          // B*S
#define DM    768
#define DMLP  3072
#define QKVN  2304
#define NHEAD 12
#define DHEAD 64
#define SEQ   1024
#define NBH   96            // B * NHEAD

// ---------------- scratch (device globals; no allocation allowed) ----------------
__device__ float g_xln[ROWS * DM];
__device__ float g_z[ROWS * DM];
__device__ float g_mid[ROWS * DM];
__device__ float g_hidden[ROWS * DMLP];
__device__ float g_wqkv[QKVN * DM];   // [N=2304][K=768] tf32-rounded
__device__ float g_wo[DM * DM];       // [N=768][K=768]
__device__ float g_win[DMLP * DM];    // [N=3072][K=768]
__device__ float g_wout[DM * DMLP];   // [N=768][K=3072]
__device__ float g_bqkv[QKVN];
__device__ __nv_bfloat16 g_qbf[NBH * SEQ * DHEAD];  // [b,h,s,d], pre-scaled 1/8
__device__ __nv_bfloat16 g_kbf[NBH * SEQ * DHEAD];
__device__ __nv_bfloat16 g_vbf[NBH * SEQ * DHEAD];

// ---------------- helpers ----------------
__device__ __forceinline__ uint32_t smem_to_u32(const void* p) {
    uint32_t a;
    asm("{ .reg .u64 t; cvta.to.shared.u64 t, %1; cvt.u32.u64 %0, t; }" : "=r"(a) : "l"(p));
    return a;
}
__device__ __forceinline__ void cp_async16(uint32_t dst, const void* src) {
    asm volatile("cp.async.cg.shared.global [%0], [%1], 16;\n" :: "r"(dst), "l"(src));
}
#define CP_COMMIT() asm volatile("cp.async.commit_group;\n" ::: "memory")
#define CP_WAIT(n)  asm volatile("cp.async.wait_group %0;\n" :: "n"(n) : "memory")

__device__ __forceinline__ void ldsm_x4(uint32_t& r0, uint32_t& r1, uint32_t& r2, uint32_t& r3,
                                        uint32_t addr) {
    asm volatile("ldmatrix.sync.aligned.m8n8.x4.shared.b16 {%0,%1,%2,%3}, [%4];"
                 : "=r"(r0), "=r"(r1), "=r"(r2), "=r"(r3) : "r"(addr));
}
__device__ __forceinline__ void ldsm_x4_trans(uint32_t& r0, uint32_t& r1, uint32_t& r2,
                                              uint32_t& r3, uint32_t addr) {
    asm volatile("ldmatrix.sync.aligned.m8n8.x4.trans.shared.b16 {%0,%1,%2,%3}, [%4];"
                 : "=r"(r0), "=r"(r1), "=r"(r2), "=r"(r3) : "r"(addr));
}
__device__ __forceinline__ void mma_tf32(float* c, const uint32_t* a, uint32_t b0, uint32_t b1) {
    asm volatile(
        "mma.sync.aligned.m16n8k8.row.col.f32.tf32.tf32.f32 "
        "{%0,%1,%2,%3}, {%4,%5,%6,%7}, {%8,%9}, {%0,%1,%2,%3};"
        : "+f"(c[0]), "+f"(c[1]), "+f"(c[2]), "+f"(c[3])
        : "r"(a[0]), "r"(a[1]), "r"(a[2]), "r"(a[3]), "r"(b0), "r"(b1));
}
__device__ __forceinline__ void mma_bf16(float* c, const uint32_t* a, uint32_t b0, uint32_t b1) {
    asm volatile(
        "mma.sync.aligned.m16n8k16.row.col.f32.bf16.bf16.f32 "
        "{%0,%1,%2,%3}, {%4,%5,%6,%7}, {%8,%9}, {%0,%1,%2,%3};"
        : "+f"(c[0]), "+f"(c[1]), "+f"(c[2]), "+f"(c[3])
        : "r"(a[0]), "r"(a[1]), "r"(a[2]), "r"(a[3]), "r"(b0), "r"(b1));
}
__device__ __forceinline__ float to_tf32(float x) {
    uint32_t u;
    asm("cvt.rna.tf32.f32 %0, %1;" : "=r"(u) : "f"(x));
    return __uint_as_float(u);
}
__device__ __forceinline__ uint32_t pack_bf2(float a, float b) {
    __nv_bfloat162 p = __floats2bfloat162_rn(a, b);
    return *(uint32_t*)&p;
}

__device__ __forceinline__ float gelu_new_f(float x) {
    float x3 = x * x * x;
    float t  = tanhf(0.7978845608028654f * (x + 0.044715f * x3));
    return 0.5f * x * (1.0f + t);
}

// ---------------- weight packing ----------------
__global__ void pack_wqkv_kernel(const float* __restrict__ WQ, const float* __restrict__ WK,
                                 const float* __restrict__ WV, const float* __restrict__ bQ,
                                 const float* __restrict__ bK, const float* __restrict__ bV) {
    int idx = blockIdx.x * 256 + threadIdx.x;
    if (idx < QKVN * DM) {
        int j = idx / DM;
        int d = idx - j * DM;
        int which = j / DM;
        int jj = j - which * DM;
        int h = jj >> 6, e = jj & 63;
        const float* W = (which == 0) ? WQ : (which == 1) ? WK : WV;
        g_wqkv[idx] = to_tf32(W[(h * DM + d) * DHEAD + e]);
    }
    if (idx < QKVN) {
        g_bqkv[idx] = (idx < DM) ? bQ[idx] : (idx < 2 * DM) ? bK[idx - DM] : bV[idx - 2 * DM];
    }
}

// in[R][C] fp32 -> out[C][R] tf32-rounded fp32
__global__ void transpose_pack_kernel(const float* __restrict__ in,
                                      float* __restrict__ out, int R, int C) {
    __shared__ float t[32][33];
    int bx = blockIdx.x * 32, by = blockIdx.y * 32;
    int x = threadIdx.x, y = threadIdx.y;
#pragma unroll
    for (int i = 0; i < 32; i += 8)
        t[y + i][x] = in[(size_t)(by + y + i) * C + bx + x];
    __syncthreads();
#pragma unroll
    for (int i = 0; i < 32; i += 8)
        out[(size_t)(bx + y + i) * R + by + x] = to_tf32(t[x][y + i]);
}

// ---------------- LayerNorm (emits tf32-rounded fp32) ----------------
__global__ void layernorm_kernel(const float* __restrict__ x, const float* __restrict__ w,
                                 const float* __restrict__ b, float* __restrict__ y) {
    int row = blockIdx.x;
    int tid = threadIdx.x;
    const float* xr = x + (size_t)row * DM;
    float v0 = xr[tid], v1 = xr[tid + 256], v2 = xr[tid + 512];
    float s  = v0 + v1 + v2;
    float ss = v0 * v0 + v1 * v1 + v2 * v2;
#pragma unroll
    for (int o = 16; o > 0; o >>= 1) {
        s  += __shfl_xor_sync(0xffffffffu, s, o);
        ss += __shfl_xor_sync(0xffffffffu, ss, o);
    }
    __shared__ float shs[8], shss[8];
    int warp = tid >> 5, lane = tid & 31;
    if (lane == 0) { shs[warp] = s; shss[warp] = ss; }
    __syncthreads();
    if (tid < 32) {
        s  = (lane < 8) ? shs[lane] : 0.f;
        ss = (lane < 8) ? shss[lane] : 0.f;
#pragma unroll
        for (int o = 4; o > 0; o >>= 1) {
            s  += __shfl_xor_sync(0xffffffffu, s, o);
            ss += __shfl_xor_sync(0xffffffffu, ss, o);
        }
        if (lane == 0) { shs[0] = s; shss[0] = ss; }
    }
    __syncthreads();
    s = shs[0]; ss = shss[0];
    float mean = s * (1.f / DM);
    float var  = ss * (1.f / DM) - mean * mean;
    float rstd = rsqrtf(var + 1e-5f);
    float* yr = y + (size_t)row * DM;
    yr[tid]       = to_tf32((v0 - mean) * rstd * w[tid]       + b[tid]);
    yr[tid + 256] = to_tf32((v1 - mean) * rstd * w[tid + 256] + b[tid + 256]);
    yr[tid + 512] = to_tf32((v2 - mean) * rstd * w[tid + 512] + b[tid + 512]);
}

// ---------------- tf32 HMMA GEMM: C[M,N] = A[M,K] x B[N,K]^T ----------------
// EPI: 1 = fp32 +bias+GELU tf32-rounded;  2 = fp32 +bias+residual;
//      3 = QKV split: bf16 to g_qbf/g_kbf/g_vbf in [b,h,s,d] (Q scaled 1/8)
#define STG_BYTES 32768   // A 16KB + B 16KB per stage
template <int EPI>
__global__ __launch_bounds__(256, 1) void gemm_mma_kernel(
    const float* __restrict__ A, const float* __restrict__ B,
    const float* __restrict__ bias, const float* __restrict__ Rres,
    float* __restrict__ Cout, int N, int K) {
    extern __shared__ char smem[];
    int tid = threadIdx.x, lane = tid & 31, wid = tid >> 5;
    int bx = blockIdx.x, by = blockIdx.y;
    int warp_m = (wid & 1) * 64;
    int warp_n = (wid >> 1) * 32;

    const float* Ab = A + (size_t)(by * 128) * K;
    const float* Bb = B + (size_t)(bx * 128) * K;
    uint32_t sbase = smem_to_u32(smem);

    float c[4][4][4];
#pragma unroll
    for (int i = 0; i < 4; i++)
#pragma unroll
        for (int j = 0; j < 4; j++)
#pragma unroll
            for (int k = 0; k < 4; k++) c[i][j][k] = 0.f;

    int T = K >> 5;

    auto load_stage = [&](int s, int kt) {
        uint32_t dstA = sbase + s * STG_BYTES;
        uint32_t dstB = dstA + 16384;
        const float* Ag = Ab + kt * 32;
        const float* Bg = Bb + kt * 32;
#pragma unroll
        for (int i = 0; i < 4; i++) {
            int idx = tid + i * 256;
            int r = idx >> 3, cc = idx & 7;
            uint32_t off = (uint32_t)(r * 128 + ((cc ^ (r & 7)) * 16));
            cp_async16(dstA + off, Ag + (size_t)r * K + cc * 4);
            cp_async16(dstB + off, Bg + (size_t)r * K + cc * 4);
        }
        CP_COMMIT();
    };

    load_stage(0, 0);
    load_stage(1, 1);

    int l7 = lane & 7;
    int lg = lane >> 3;

    for (int t = 0; t < T; t++) {
        if (t + 2 < T) load_stage((t + 2) % 3, t + 2);
        if (t + 2 < T)      { CP_WAIT(2); }
        else if (t + 1 < T) { CP_WAIT(1); }
        else                { CP_WAIT(0); }
        __syncthreads();

        uint32_t sA = sbase + (t % 3) * STG_BYTES;
        uint32_t sB = sA + 16384;
#pragma unroll
        for (int ks = 0; ks < 4; ks++) {
            uint32_t a[4][4];
#pragma unroll
            for (int i = 0; i < 4; i++) {
                int row = warp_m + i * 16 + ((lg & 1) << 3) + l7;
                int chunk = ks * 2 + (lg >> 1);
                uint32_t addr = sA + row * 128 + ((chunk ^ (row & 7)) << 4);
                ldsm_x4(a[i][0], a[i][1], a[i][2], a[i][3], addr);
            }
            uint32_t b[2][4];
#pragma unroll
            for (int j = 0; j < 2; j++) {
                int row = warp_n + (j * 2 + (lg >> 1)) * 8 + l7;
                int chunk = ks * 2 + (lg & 1);
                uint32_t addr = sB + row * 128 + ((chunk ^ (row & 7)) << 4);
                ldsm_x4(b[j][0], b[j][1], b[j][2], b[j][3], addr);
            }
#pragma unroll
            for (int i = 0; i < 4; i++)
#pragma unroll
                for (int jn = 0; jn < 4; jn++)
                    mma_tf32(c[i][jn], a[i], b[jn >> 1][(jn & 1) * 2],
                             b[jn >> 1][(jn & 1) * 2 + 1]);
        }
        __syncthreads();
    }

    int quad = lane >> 2, tc2 = (lane & 3) * 2;
#pragma unroll
    for (int i = 0; i < 4; i++) {
#pragma unroll
        for (int jj = 0; jj < 4; jj++) {
            int row0 = by * 128 + warp_m + i * 16 + quad;
            int col  = bx * 128 + warp_n + jj * 8 + tc2;
            float bb0 = bias[col], bb1 = bias[col + 1];
            float v0 = c[i][jj][0] + bb0, v1 = c[i][jj][1] + bb1;
            float v2 = c[i][jj][2] + bb0, v3 = c[i][jj][3] + bb1;
            if (EPI == 3) {
                // split to Q/K/V bf16, [b,h,s,d] layout
                int which = col / DM;
                int rem = col - which * DM;
                int h = rem >> 6, e = rem & 63;
                __nv_bfloat16* dstb = (which == 0) ? g_qbf : (which == 1) ? g_kbf : g_vbf;
                float sc = (which == 0) ? 0.125f : 1.0f;
#pragma unroll
                for (int rr = 0; rr < 2; rr++) {
                    int rg = row0 + rr * 8;
                    int b_ = rg >> 10, s_ = rg & 1023;
                    size_t di = ((size_t)(b_ * NHEAD + h) * SEQ + s_) * DHEAD + e;
                    float x0 = (rr ? v2 : v0) * sc, x1 = (rr ? v3 : v1) * sc;
                    *(uint32_t*)(dstb + di) = pack_bf2(x0, x1);
                }
            } else {
                if (EPI == 1) {
                    v0 = to_tf32(gelu_new_f(v0)); v1 = to_tf32(gelu_new_f(v1));
                    v2 = to_tf32(gelu_new_f(v2)); v3 = to_tf32(gelu_new_f(v3));
                }
                if (EPI == 2) {
                    const float2 r0 = *(const float2*)(Rres + (size_t)row0 * N + col);
                    const float2 r1 = *(const float2*)(Rres + (size_t)(row0 + 8) * N + col);
                    v0 += r0.x; v1 += r0.y; v2 += r1.x; v3 += r1.y;
                }
                *(float2*)(Cout + (size_t)row0 * N + col)       = make_float2(v0, v1);
                *(float2*)(Cout + (size_t)(row0 + 8) * N + col) = make_float2(v2, v3);
            }
        }
    }
}

// ---------------- FA2-style bf16 tensor-core causal attention ----------------
// grid = (16 q-tiles of 64 rows, 96 b*h). 128 threads = 4 warps, 16 q-rows/warp.
// Q*K^T and P*V via mma.m16n8k16.bf16, fp32 online softmax, P packed in-register.
__global__ __launch_bounds__(128) void attn_kernel(float* __restrict__ z) {
    __shared__ __align__(128) char sm[8192 + 2 * 16384];   // Q | {K,V} x2 stages
    int qt = blockIdx.x;
    int bh = blockIdx.y;
    int b = bh / NHEAD, h = bh - b * NHEAD;
    int tid = threadIdx.x, lane = tid & 31, w = tid >> 5;

    uint32_t sQ = smem_to_u32(sm);
    const __nv_bfloat16* Qg = g_qbf + ((size_t)bh * SEQ + qt * 64) * DHEAD;
    const __nv_bfloat16* Kg = g_kbf + (size_t)bh * SEQ * DHEAD;
    const __nv_bfloat16* Vg = g_vbf + (size_t)bh * SEQ * DHEAD;

    auto load64 = [&](uint32_t dst, const __nv_bfloat16* src) {
#pragma unroll
        for (int i = 0; i < 4; i++) {
            int idx = tid + i * 128;
            int r = idx >> 3, cc = idx & 7;
            uint32_t off = (uint32_t)(r * 128 + ((cc ^ (r & 7)) << 4));
            cp_async16(dst + off, src + (size_t)r * DHEAD + cc * 8);
        }
    };
    auto load_kv = [&](int s, int jt) {
        uint32_t base = sQ + 8192 + s * 16384;
        load64(base, Kg + (size_t)jt * 64 * DHEAD);
        load64(base + 8192, Vg + (size_t)jt * 64 * DHEAD);
        CP_COMMIT();
    };

    // Q tile + KV tile 0
    load64(sQ, Qg);
    CP_COMMIT();
    load_kv(0, 0);
    CP_WAIT(0);
    __syncthreads();

    // Q fragments (A, m16n8k16): 4 k16-steps x 4 regs
    int l7 = lane & 7, lg = lane >> 3;
    uint32_t qa[4][4];
#pragma unroll
    for (int ks = 0; ks < 4; ks++) {
        int row = w * 16 + ((lg & 1) << 3) + l7;
        int chunk = ks * 2 + (lg >> 1);
        uint32_t addr = sQ + row * 128 + ((chunk ^ (row & 7)) << 4);
        ldsm_x4(qa[ks][0], qa[ks][1], qa[ks][2], qa[ks][3], addr);
    }

    int quad = lane >> 2, tc2 = (lane & 3) * 2;
    float acc[8][4];
#pragma unroll
    for (int j = 0; j < 8; j++)
#pragma unroll
        for (int v = 0; v < 4; v++) acc[j][v] = 0.f;
    float m0 = -INFINITY, m1 = -INFINITY, l0 = 0.f, l1 = 0.f;

    for (int jt = 0; jt <= qt; jt++) {
        if (jt < qt) { load_kv((jt + 1) & 1, jt + 1); CP_WAIT(1); }
        else         { CP_WAIT(0); }
        __syncthreads();
        uint32_t sK = sQ + 8192 + (jt & 1) * 16384;
        uint32_t sV = sK + 8192;

        // S = Q x K^T  (16 rows x 64 keys per warp)
        float c[8][4];
#pragma unroll
        for (int j = 0; j < 8; j++)
#pragma unroll
            for (int v = 0; v < 4; v++) c[j][v] = 0.f;
#pragma unroll
        for (int ks = 0; ks < 4; ks++) {
            uint32_t kb[4][4];
#pragma unroll
            for (int g = 0; g < 2; g++) {
                // two ldsm per 32 keys: covers key groups 4g, 4g+1 (n-tiles 4g..4g+3)
#pragma unroll
                for (int gg = 0; gg < 2; gg++) {
                    int row = (g * 2 + gg) * 16 + (lg >> 1) * 8 + l7;
                    int chunk = ks * 2 + (lg & 1);
                    uint32_t addr = sK + row * 128 + ((chunk ^ (row & 7)) << 4);
                    ldsm_x4(kb[g * 2 + gg][0], kb[g * 2 + gg][1],
                            kb[g * 2 + gg][2], kb[g * 2 + gg][3], addr);
                }
            }
#pragma unroll
            for (int j = 0; j < 8; j++)
                mma_bf16(c[j], qa[ks], kb[j >> 1][(j & 1) * 2], kb[j >> 1][(j & 1) * 2 + 1]);
        }

        // causal mask on the diagonal tile
        if (jt == qt) {
            int r0 = w * 16 + quad;
#pragma unroll
            for (int j = 0; j < 8; j++) {
                int kc = j * 8 + tc2;
                if (kc > r0)     c[j][0] = -INFINITY;
                if (kc + 1 > r0) c[j][1] = -INFINITY;
                if (kc > r0 + 8)     c[j][2] = -INFINITY;
                if (kc + 1 > r0 + 8) c[j][3] = -INFINITY;
            }
        }

        // online softmax (fp32)
        float mx0 = -INFINITY, mx1 = -INFINITY;
#pragma unroll
        for (int j = 0; j < 8; j++) {
            mx0 = fmaxf(mx0, fmaxf(c[j][0], c[j][1]));
            mx1 = fmaxf(mx1, fmaxf(c[j][2], c[j][3]));
        }
        mx0 = fmaxf(mx0, __shfl_xor_sync(0xffffffffu, mx0, 1));
        mx0 = fmaxf(mx0, __shfl_xor_sync(0xffffffffu, mx0, 2));
        mx1 = fmaxf(mx1, __shfl_xor_sync(0xffffffffu, mx1, 1));
        mx1 = fmaxf(mx1, __shfl_xor_sync(0xffffffffu, mx1, 2));
        float mn0 = fmaxf(m0, mx0), mn1 = fmaxf(m1, mx1);
        float corr0 = __expf(m0 - mn0), corr1 = __expf(m1 - mn1);
        l0 *= corr0; l1 *= corr1;
#pragma unroll
        for (int j = 0; j < 8; j++) {
            c[j][0] = __expf(c[j][0] - mn0);
            c[j][1] = __expf(c[j][1] - mn0);
            c[j][2] = __expf(c[j][2] - mn1);
            c[j][3] = __expf(c[j][3] - mn1);
            l0 += c[j][0] + c[j][1];
            l1 += c[j][2] + c[j][3];
#pragma unroll
            for (int v = 0; v < 4; v++)
                acc[j][v] *= (v < 2) ? corr0 : corr1;
        }
        m0 = mn0; m1 = mn1;

        // P x V : A = P (bf16 packed from c), B = V^T via ldmatrix.trans
#pragma unroll
        for (int t = 0; t < 4; t++) {
            uint32_t pa[4];
            pa[0] = pack_bf2(c[2 * t][0], c[2 * t][1]);
            pa[1] = pack_bf2(c[2 * t][2], c[2 * t][3]);
            pa[2] = pack_bf2(c[2 * t + 1][0], c[2 * t + 1][1]);
            pa[3] = pack_bf2(c[2 * t + 1][2], c[2 * t + 1][3]);
#pragma unroll
            for (int nb = 0; nb < 4; nb++) {
                uint32_t vb[4];
                int key = t * 16 + ((lg & 1) << 3) + l7;
                int chunk = nb * 2 + (lg >> 1);
                uint32_t addr = sV + key * 128 + ((chunk ^ (key & 7)) << 4);
                ldsm_x4_trans(vb[0], vb[1], vb[2], vb[3], addr);
                mma_bf16(acc[nb * 2],     pa, vb[0], vb[1]);
                mma_bf16(acc[nb * 2 + 1], pa, vb[2], vb[3]);
            }
        }
        __syncthreads();
    }

    // finalize
    l0 += __shfl_xor_sync(0xffffffffu, l0, 1);
    l0 += __shfl_xor_sync(0xffffffffu, l0, 2);
    l1 += __shfl_xor_sync(0xffffffffu, l1, 1);
    l1 += __shfl_xor_sync(0xffffffffu, l1, 2);
    float inv0 = 1.f / l0, inv1 = 1.f / l1;
    int r0g = b * SEQ + qt * 64 + w * 16 + quad;
#pragma unroll
    for (int j = 0; j < 8; j++) {
        int col = h * 64 + j * 8 + tc2;
        *(float2*)(z + (size_t)r0g * DM + col) =
            make_float2(to_tf32(acc[j][0] * inv0), to_tf32(acc[j][1] * inv0));
        *(float2*)(z + (size_t)(r0g + 8) * DM + col) =
            make_float2(to_tf32(acc[j][2] * inv1), to_tf32(acc[j][3] * inv1));
    }
}

// ---------------- launch ----------------
extern "C" void kernel_launch(void* const* d_in, const int* in_sizes, int n_in,
                              void* d_out, int out_size) {
    const float* resid_pre = (const float*)d_in[0];
    const float* W_Q  = (const float*)d_in[1];
    const float* W_K  = (const float*)d_in[2];
    const float* W_V  = (const float*)d_in[3];
    const float* W_O  = (const float*)d_in[4];
    const float* b_Q  = (const float*)d_in[5];
    const float* b_K  = (const float*)d_in[6];
    const float* b_V  = (const float*)d_in[7];
    const float* b_O  = (const float*)d_in[8];
    const float* ln1w = (const float*)d_in[9];
    const float* ln1b = (const float*)d_in[10];
    const float* ln2w = (const float*)d_in[11];
    const float* ln2b = (const float*)d_in[12];
    const float* W_in  = (const float*)d_in[13];
    const float* b_in  = (const float*)d_in[14];
    const float* W_out = (const float*)d_in[15];
    const float* b_out = (const float*)d_in[16];
    float* out = (float*)d_out;

    float *xln, *z, *mid, *hidden, *wqkv, *wo, *win, *wout, *bqkv;
    cudaGetSymbolAddress((void**)&xln,    g_xln);
    cudaGetSymbolAddress((void**)&z,      g_z);
    cudaGetSymbolAddress((void**)&mid,    g_mid);
    cudaGetSymbolAddress((void**)&hidden, g_hidden);
    cudaGetSymbolAddress((void**)&wqkv,   g_wqkv);
    cudaGetSymbolAddress((void**)&wo,     g_wo);
    cudaGetSymbolAddress((void**)&win,    g_win);
    cudaGetSymbolAddress((void**)&wout,   g_wout);
    cudaGetSymbolAddress((void**)&bqkv,   g_bqkv);

    const int SMEM = 3 * STG_BYTES;
    cudaFuncSetAttribute(gemm_mma_kernel<1>, cudaFuncAttributeMaxDynamicSharedMemorySize, SMEM);
    cudaFuncSetAttribute(gemm_mma_kernel<2>, cudaFuncAttributeMaxDynamicSharedMemorySize, SMEM);
    cudaFuncSetAttribute(gemm_mma_kernel<3>, cudaFuncAttributeMaxDynamicSharedMemorySize, SMEM);

    // weight packing (tf32-rounded fp32, [N,K] layouts)
    pack_wqkv_kernel<<<(QKVN * DM + 255) / 256, 256>>>(W_Q, W_K, W_V, b_Q, b_K, b_V);
    transpose_pack_kernel<<<dim3(DM / 32, DM / 32),   dim3(32, 8)>>>(W_O,  wo,   DM,   DM);
    transpose_pack_kernel<<<dim3(DMLP / 32, DM / 32), dim3(32, 8)>>>(W_in, win,  DM,   DMLP);
    transpose_pack_kernel<<<dim3(DM / 32, DMLP / 32), dim3(32, 8)>>>(W_out, wout, DMLP, DM);

    // 1) LN1
    layernorm_kernel<<<ROWS, 256>>>(resid_pre, ln1w, ln1b, xln);
    // 2) fused QKV projection -> bf16 Q/K/V in [b,h,s,d]
    gemm_mma_kernel<3><<<dim3(QKVN / 128, ROWS / 128), 256, SMEM>>>(xln, wqkv, bqkv, nullptr,
                                                                    nullptr, QKVN, DM);
    // 3) tensor-core causal attention -> z (tf32-rounded fp32)
    attn_kernel<<<dim3(SEQ / 64, NBH), 128>>>(z);
    // 4) O projection + bias + residual -> mid
    gemm_mma_kernel<2><<<dim3(DM / 128, ROWS / 128), 256, SMEM>>>(z, wo, b_O, resid_pre,
                                                                  mid, DM, DM);
    // 5) LN2
    layernorm_kernel<<<ROWS, 256>>>(mid, ln2w, ln2b, xln);
    // 6) MLP in + bias + GELU
    gemm_mma_kernel<1><<<dim3(DMLP / 128, ROWS / 128), 256, SMEM>>>(xln, win, b_in, nullptr,
                                                                    hidden, DMLP, DM);
    // 7) MLP out + bias + residual -> out
    gemm_mma_kernel<2><<<dim3(DM / 128, ROWS / 128), 256, SMEM>>>(hidden, wout, b_out, mid,
                                                                  out, DM, DMLP);
}

// round 7
// speedup vs baseline: 4.8841x; 1.3234x over previous
#include <cuda_runtime.h>
#include <cuda_bf16.h>
#include <math.h>
#include <stdint.h>

#define ROWS  8192          // B*S
#define DM    768
#define DMLP  3072
#define QKVN  2304
#define NHEAD 12
#define DHEAD 64
#define SEQ   1024
#define NBH   96            // B * NHEAD

// ---------------- scratch (device globals; no allocation allowed) ----------------
__device__ __nv_bfloat16 g_xln_bf[ROWS * DM];       // LN1 out (bf16)
__device__ float         g_xln[ROWS * DM];          // LN2 out (tf32-rounded fp32)
__device__ __nv_bfloat16 g_z_bf[ROWS * DM];         // attention out (bf16)
__device__ float         g_mid[ROWS * DM];
__device__ float         g_hidden[ROWS * DMLP];
__device__ __nv_bfloat16 g_wqkv_bf[QKVN * DM];      // [N=2304][K=768] bf16
__device__ __nv_bfloat16 g_wo_bf[DM * DM];          // [N=768][K=768] bf16
__device__ float         g_win[DMLP * DM];          // [N=3072][K=768] tf32
__device__ float         g_wout[DM * DMLP];         // [N=768][K=3072] tf32
__device__ float         g_bqkv[QKVN];
__device__ __nv_bfloat16 g_qbf[NBH * SEQ * DHEAD];  // [b,h,s,d], pre-scaled 1/8
__device__ __nv_bfloat16 g_kbf[NBH * SEQ * DHEAD];
__device__ __nv_bfloat16 g_vbf[NBH * SEQ * DHEAD];

// ---------------- helpers ----------------
__device__ __forceinline__ uint32_t smem_to_u32(const void* p) {
    uint32_t a;
    asm("{ .reg .u64 t; cvta.to.shared.u64 t, %1; cvt.u32.u64 %0, t; }" : "=r"(a) : "l"(p));
    return a;
}
__device__ __forceinline__ void cp_async16(uint32_t dst, const void* src) {
    asm volatile("cp.async.cg.shared.global [%0], [%1], 16;\n" :: "r"(dst), "l"(src));
}
#define CP_COMMIT() asm volatile("cp.async.commit_group;\n" ::: "memory")
#define CP_WAIT(n)  asm volatile("cp.async.wait_group %0;\n" :: "n"(n) : "memory")

__device__ __forceinline__ void ldsm_x4(uint32_t& r0, uint32_t& r1, uint32_t& r2, uint32_t& r3,
                                        uint32_t addr) {
    asm volatile("ldmatrix.sync.aligned.m8n8.x4.shared.b16 {%0,%1,%2,%3}, [%4];"
                 : "=r"(r0), "=r"(r1), "=r"(r2), "=r"(r3) : "r"(addr));
}
__device__ __forceinline__ void ldsm_x4_trans(uint32_t& r0, uint32_t& r1, uint32_t& r2,
                                              uint32_t& r3, uint32_t addr) {
    asm volatile("ldmatrix.sync.aligned.m8n8.x4.trans.shared.b16 {%0,%1,%2,%3}, [%4];"
                 : "=r"(r0), "=r"(r1), "=r"(r2), "=r"(r3) : "r"(addr));
}
__device__ __forceinline__ void mma_tf32(float* c, const uint32_t* a, uint32_t b0, uint32_t b1) {
    asm volatile(
        "mma.sync.aligned.m16n8k8.row.col.f32.tf32.tf32.f32 "
        "{%0,%1,%2,%3}, {%4,%5,%6,%7}, {%8,%9}, {%0,%1,%2,%3};"
        : "+f"(c[0]), "+f"(c[1]), "+f"(c[2]), "+f"(c[3])
        : "r"(a[0]), "r"(a[1]), "r"(a[2]), "r"(a[3]), "r"(b0), "r"(b1));
}
__device__ __forceinline__ void mma_bf16(float* c, const uint32_t* a, uint32_t b0, uint32_t b1) {
    asm volatile(
        "mma.sync.aligned.m16n8k16.row.col.f32.bf16.bf16.f32 "
        "{%0,%1,%2,%3}, {%4,%5,%6,%7}, {%8,%9}, {%0,%1,%2,%3};"
        : "+f"(c[0]), "+f"(c[1]), "+f"(c[2]), "+f"(c[3])
        : "r"(a[0]), "r"(a[1]), "r"(a[2]), "r"(a[3]), "r"(b0), "r"(b1));
}
__device__ __forceinline__ float to_tf32(float x) {
    uint32_t u;
    asm("cvt.rna.tf32.f32 %0, %1;" : "=r"(u) : "f"(x));
    return __uint_as_float(u);
}
__device__ __forceinline__ uint32_t pack_bf2(float a, float b) {
    __nv_bfloat162 p = __floats2bfloat162_rn(a, b);
    return *(uint32_t*)&p;
}
__device__ __forceinline__ float gelu_new_f(float x) {
    float x3 = x * x * x;
    float t  = tanhf(0.7978845608028654f * (x + 0.044715f * x3));
    return 0.5f * x * (1.0f + t);
}

// ---------------- weight packing ----------------
__global__ void pack_wqkv_kernel(const float* __restrict__ WQ, const float* __restrict__ WK,
                                 const float* __restrict__ WV, const float* __restrict__ bQ,
                                 const float* __restrict__ bK, const float* __restrict__ bV) {
    int idx = blockIdx.x * 256 + threadIdx.x;
    if (idx < QKVN * DM) {
        int j = idx / DM;
        int d = idx - j * DM;
        int which = j / DM;
        int jj = j - which * DM;
        int h = jj >> 6, e = jj & 63;
        const float* W = (which == 0) ? WQ : (which == 1) ? WK : WV;
        g_wqkv_bf[idx] = __float2bfloat16(W[(h * DM + d) * DHEAD + e]);
    }
    if (idx < QKVN) {
        g_bqkv[idx] = (idx < DM) ? bQ[idx] : (idx < 2 * DM) ? bK[idx - DM] : bV[idx - 2 * DM];
    }
}

// in[R][C] fp32 -> out[C][R], OUT=0: tf32-rounded fp32, OUT=1: bf16
template <int OUT>
__global__ void transpose_pack_kernel(const float* __restrict__ in, void* __restrict__ outp,
                                      int R, int C) {
    __shared__ float t[32][33];
    int bx = blockIdx.x * 32, by = blockIdx.y * 32;
    int x = threadIdx.x, y = threadIdx.y;
#pragma unroll
    for (int i = 0; i < 32; i += 8)
        t[y + i][x] = in[(size_t)(by + y + i) * C + bx + x];
    __syncthreads();
#pragma unroll
    for (int i = 0; i < 32; i += 8) {
        size_t di = (size_t)(bx + y + i) * R + by + x;
        if (OUT == 0) ((float*)outp)[di] = to_tf32(t[x][y + i]);
        else          ((__nv_bfloat16*)outp)[di] = __float2bfloat16(t[x][y + i]);
    }
}

// ---------------- LayerNorm, OUT=0: tf32-rounded fp32, OUT=1: bf16 ----------------
template <int OUT>
__global__ void layernorm_kernel(const float* __restrict__ x, const float* __restrict__ w,
                                 const float* __restrict__ b, void* __restrict__ yp) {
    int row = blockIdx.x;
    int tid = threadIdx.x;
    const float* xr = x + (size_t)row * DM;
    float v0 = xr[tid], v1 = xr[tid + 256], v2 = xr[tid + 512];
    float s  = v0 + v1 + v2;
    float ss = v0 * v0 + v1 * v1 + v2 * v2;
#pragma unroll
    for (int o = 16; o > 0; o >>= 1) {
        s  += __shfl_xor_sync(0xffffffffu, s, o);
        ss += __shfl_xor_sync(0xffffffffu, ss, o);
    }
    __shared__ float shs[8], shss[8];
    int warp = tid >> 5, lane = tid & 31;
    if (lane == 0) { shs[warp] = s; shss[warp] = ss; }
    __syncthreads();
    if (tid < 32) {
        s  = (lane < 8) ? shs[lane] : 0.f;
        ss = (lane < 8) ? shss[lane] : 0.f;
#pragma unroll
        for (int o = 4; o > 0; o >>= 1) {
            s  += __shfl_xor_sync(0xffffffffu, s, o);
            ss += __shfl_xor_sync(0xffffffffu, ss, o);
        }
        if (lane == 0) { shs[0] = s; shss[0] = ss; }
    }
    __syncthreads();
    s = shs[0]; ss = shss[0];
    float mean = s * (1.f / DM);
    float var  = ss * (1.f / DM) - mean * mean;
    float rstd = rsqrtf(var + 1e-5f);
    float o0 = (v0 - mean) * rstd * w[tid]       + b[tid];
    float o1 = (v1 - mean) * rstd * w[tid + 256] + b[tid + 256];
    float o2 = (v2 - mean) * rstd * w[tid + 512] + b[tid + 512];
    if (OUT == 0) {
        float* yr = (float*)yp + (size_t)row * DM;
        yr[tid] = to_tf32(o0); yr[tid + 256] = to_tf32(o1); yr[tid + 512] = to_tf32(o2);
    } else {
        __nv_bfloat16* yr = (__nv_bfloat16*)yp + (size_t)row * DM;
        yr[tid] = __float2bfloat16(o0);
        yr[tid + 256] = __float2bfloat16(o1);
        yr[tid + 512] = __float2bfloat16(o2);
    }
}

#define STG_BYTES 32768   // A 16KB + B 16KB per stage

// ---------------- bf16 HMMA GEMM: C[M,N] = A[M,K] x B[N,K]^T (K=64/stage, 3 stages) ----
// EPI: 2 = fp32 +bias+residual;  3 = QKV split to bf16 g_qbf/g_kbf/g_vbf (Q scaled 1/8)
template <int EPI>
__global__ __launch_bounds__(256, 1) void gemm_bf16_kernel(
    const __nv_bfloat16* __restrict__ A, const __nv_bfloat16* __restrict__ B,
    const float* __restrict__ bias, const float* __restrict__ Rres,
    float* __restrict__ Cout, int N, int K) {
    extern __shared__ char smem[];
    int tid = threadIdx.x, lane = tid & 31, wid = tid >> 5;
    int bx = blockIdx.x, by = blockIdx.y;
    int warp_m = (wid & 1) * 64;
    int warp_n = (wid >> 1) * 32;

    const __nv_bfloat16* Ab = A + (size_t)(by * 128) * K;
    const __nv_bfloat16* Bb = B + (size_t)(bx * 128) * K;
    uint32_t sbase = smem_to_u32(smem);

    float c[4][4][4];
#pragma unroll
    for (int i = 0; i < 4; i++)
#pragma unroll
        for (int j = 0; j < 4; j++)
#pragma unroll
            for (int k = 0; k < 4; k++) c[i][j][k] = 0.f;

    int T = K >> 6;

    auto load_stage = [&](int s, int kt) {
        uint32_t dstA = sbase + s * STG_BYTES;
        uint32_t dstB = dstA + 16384;
        const __nv_bfloat16* Ag = Ab + kt * 64;
        const __nv_bfloat16* Bg = Bb + kt * 64;
#pragma unroll
        for (int i = 0; i < 4; i++) {
            int idx = tid + i * 256;
            int r = idx >> 3, cc = idx & 7;
            uint32_t off = (uint32_t)(r * 128 + ((cc ^ (r & 7)) * 16));
            cp_async16(dstA + off, Ag + (size_t)r * K + cc * 8);
            cp_async16(dstB + off, Bg + (size_t)r * K + cc * 8);
        }
        CP_COMMIT();
    };

    load_stage(0, 0);
    load_stage(1, 1);

    int l7 = lane & 7;
    int a_r = ((lane >> 3) & 1) * 8 + l7;
    int a_k = lane >> 4;
    int b_r = (lane >> 4) * 8 + l7;
    int b_k = (lane >> 3) & 1;

    for (int t = 0; t < T; t++) {
        if (t + 2 < T) load_stage((t + 2) % 3, t + 2);
        if (t + 2 < T)      { CP_WAIT(2); }
        else if (t + 1 < T) { CP_WAIT(1); }
        else                { CP_WAIT(0); }
        __syncthreads();

        uint32_t sA = sbase + (t % 3) * STG_BYTES;
        uint32_t sB = sA + 16384;
#pragma unroll
        for (int ks = 0; ks < 4; ks++) {
            uint32_t a[4][4];
#pragma unroll
            for (int i = 0; i < 4; i++) {
                int row = warp_m + i * 16 + a_r;
                uint32_t addr = sA + row * 128 + (((ks * 2 + a_k) ^ l7) * 16);
                ldsm_x4(a[i][0], a[i][1], a[i][2], a[i][3], addr);
            }
            uint32_t b[2][4];
#pragma unroll
            for (int j = 0; j < 2; j++) {
                int row = warp_n + j * 16 + b_r;
                uint32_t addr = sB + row * 128 + (((ks * 2 + b_k) ^ l7) * 16);
                ldsm_x4(b[j][0], b[j][1], b[j][2], b[j][3], addr);
            }
#pragma unroll
            for (int i = 0; i < 4; i++)
#pragma unroll
                for (int jj = 0; jj < 4; jj++)
                    mma_bf16(c[i][jj], a[i], b[jj >> 1][(jj & 1) * 2],
                             b[jj >> 1][(jj & 1) * 2 + 1]);
        }
        __syncthreads();
    }

    int quad = lane >> 2, tc2 = (lane & 3) * 2;
#pragma unroll
    for (int i = 0; i < 4; i++) {
#pragma unroll
        for (int jj = 0; jj < 4; jj++) {
            int row0 = by * 128 + warp_m + i * 16 + quad;
            int col  = bx * 128 + warp_n + jj * 8 + tc2;
            float bb0 = bias[col], bb1 = bias[col + 1];
            float v0 = c[i][jj][0] + bb0, v1 = c[i][jj][1] + bb1;
            float v2 = c[i][jj][2] + bb0, v3 = c[i][jj][3] + bb1;
            if (EPI == 3) {
                int which = col / DM;
                int rem = col - which * DM;
                int h = rem >> 6, e = rem & 63;
                __nv_bfloat16* dstb = (which == 0) ? g_qbf : (which == 1) ? g_kbf : g_vbf;
                float sc = (which == 0) ? 0.125f : 1.0f;
#pragma unroll
                for (int rr = 0; rr < 2; rr++) {
                    int rg = row0 + rr * 8;
                    int b_ = rg >> 10, s_ = rg & 1023;
                    size_t di = ((size_t)(b_ * NHEAD + h) * SEQ + s_) * DHEAD + e;
                    float x0 = (rr ? v2 : v0) * sc, x1 = (rr ? v3 : v1) * sc;
                    *(uint32_t*)(dstb + di) = pack_bf2(x0, x1);
                }
            } else {
                const float2 r0 = *(const float2*)(Rres + (size_t)row0 * N + col);
                const float2 r1 = *(const float2*)(Rres + (size_t)(row0 + 8) * N + col);
                v0 += r0.x; v1 += r0.y; v2 += r1.x; v3 += r1.y;
                *(float2*)(Cout + (size_t)row0 * N + col)       = make_float2(v0, v1);
                *(float2*)(Cout + (size_t)(row0 + 8) * N + col) = make_float2(v2, v3);
            }
        }
    }
}

// ---------------- tf32 HMMA GEMM (K=32/stage, 2 stages, 2 CTA/SM) ----------------
// EPI: 1 = fp32 +bias+GELU tf32-rounded;  2 = fp32 +bias+residual
template <int EPI>
__global__ __launch_bounds__(256, 2) void gemm_tf32_kernel(
    const float* __restrict__ A, const float* __restrict__ B,
    const float* __restrict__ bias, const float* __restrict__ Rres,
    float* __restrict__ Cout, int N, int K) {
    extern __shared__ char smem[];
    int tid = threadIdx.x, lane = tid & 31, wid = tid >> 5;
    int bx = blockIdx.x, by = blockIdx.y;
    int warp_m = (wid & 1) * 64;
    int warp_n = (wid >> 1) * 32;

    const float* Ab = A + (size_t)(by * 128) * K;
    const float* Bb = B + (size_t)(bx * 128) * K;
    uint32_t sbase = smem_to_u32(smem);

    float c[4][4][4];
#pragma unroll
    for (int i = 0; i < 4; i++)
#pragma unroll
        for (int j = 0; j < 4; j++)
#pragma unroll
            for (int k = 0; k < 4; k++) c[i][j][k] = 0.f;

    int T = K >> 5;

    auto load_stage = [&](int s, int kt) {
        uint32_t dstA = sbase + s * STG_BYTES;
        uint32_t dstB = dstA + 16384;
        const float* Ag = Ab + kt * 32;
        const float* Bg = Bb + kt * 32;
#pragma unroll
        for (int i = 0; i < 4; i++) {
            int idx = tid + i * 256;
            int r = idx >> 3, cc = idx & 7;
            uint32_t off = (uint32_t)(r * 128 + ((cc ^ (r & 7)) * 16));
            cp_async16(dstA + off, Ag + (size_t)r * K + cc * 4);
            cp_async16(dstB + off, Bg + (size_t)r * K + cc * 4);
        }
        CP_COMMIT();
    };

    load_stage(0, 0);
    load_stage(1, 1);

    int l7 = lane & 7;
    int lg = lane >> 3;

    for (int t = 0; t < T; t++) {
        if (t + 1 < T) { CP_WAIT(1); } else { CP_WAIT(0); }
        __syncthreads();

        uint32_t sA = sbase + (t & 1) * STG_BYTES;
        uint32_t sB = sA + 16384;
#pragma unroll
        for (int ks = 0; ks < 4; ks++) {
            uint32_t a[4][4];
#pragma unroll
            for (int i = 0; i < 4; i++) {
                int row = warp_m + i * 16 + ((lg & 1) << 3) + l7;
                int chunk = ks * 2 + (lg >> 1);
                uint32_t addr = sA + row * 128 + ((chunk ^ (row & 7)) << 4);
                ldsm_x4(a[i][0], a[i][1], a[i][2], a[i][3], addr);
            }
            uint32_t b[2][4];
#pragma unroll
            for (int j = 0; j < 2; j++) {
                int row = warp_n + (j * 2 + (lg >> 1)) * 8 + l7;
                int chunk = ks * 2 + (lg & 1);
                uint32_t addr = sB + row * 128 + ((chunk ^ (row & 7)) << 4);
                ldsm_x4(b[j][0], b[j][1], b[j][2], b[j][3], addr);
            }
#pragma unroll
            for (int i = 0; i < 4; i++)
#pragma unroll
                for (int jn = 0; jn < 4; jn++)
                    mma_tf32(c[i][jn], a[i], b[jn >> 1][(jn & 1) * 2],
                             b[jn >> 1][(jn & 1) * 2 + 1]);
        }
        __syncthreads();
        if (t + 2 < T) load_stage(t & 1, t + 2);
    }

    int quad = lane >> 2, tc2 = (lane & 3) * 2;
#pragma unroll
    for (int i = 0; i < 4; i++) {
#pragma unroll
        for (int jj = 0; jj < 4; jj++) {
            int row0 = by * 128 + warp_m + i * 16 + quad;
            int col  = bx * 128 + warp_n + jj * 8 + tc2;
            float bb0 = bias[col], bb1 = bias[col + 1];
            float v0 = c[i][jj][0] + bb0, v1 = c[i][jj][1] + bb1;
            float v2 = c[i][jj][2] + bb0, v3 = c[i][jj][3] + bb1;
            if (EPI == 1) {
                v0 = to_tf32(gelu_new_f(v0)); v1 = to_tf32(gelu_new_f(v1));
                v2 = to_tf32(gelu_new_f(v2)); v3 = to_tf32(gelu_new_f(v3));
            }
            if (EPI == 2) {
                const float2 r0 = *(const float2*)(Rres + (size_t)row0 * N + col);
                const float2 r1 = *(const float2*)(Rres + (size_t)(row0 + 8) * N + col);
                v0 += r0.x; v1 += r0.y; v2 += r1.x; v3 += r1.y;
            }
            *(float2*)(Cout + (size_t)row0 * N + col)       = make_float2(v0, v1);
            *(float2*)(Cout + (size_t)(row0 + 8) * N + col) = make_float2(v2, v3);
        }
    }
}

// ---------------- FA2-style bf16 tensor-core causal attention ----------------
__global__ __launch_bounds__(128) void attn_kernel(__nv_bfloat16* __restrict__ z) {
    __shared__ __align__(128) char sm[8192 + 2 * 16384];   // Q | {K,V} x2 stages
    int qt = blockIdx.x;
    int bh = blockIdx.y;
    int b = bh / NHEAD, h = bh - b * NHEAD;
    int tid = threadIdx.x, lane = tid & 31, w = tid >> 5;

    uint32_t sQ = smem_to_u32(sm);
    const __nv_bfloat16* Qg = g_qbf + ((size_t)bh * SEQ + qt * 64) * DHEAD;
    const __nv_bfloat16* Kg = g_kbf + (size_t)bh * SEQ * DHEAD;
    const __nv_bfloat16* Vg = g_vbf + (size_t)bh * SEQ * DHEAD;

    auto load64 = [&](uint32_t dst, const __nv_bfloat16* src) {
#pragma unroll
        for (int i = 0; i < 4; i++) {
            int idx = tid + i * 128;
            int r = idx >> 3, cc = idx & 7;
            uint32_t off = (uint32_t)(r * 128 + ((cc ^ (r & 7)) << 4));
            cp_async16(dst + off, src + (size_t)r * DHEAD + cc * 8);
        }
    };
    auto load_kv = [&](int s, int jt) {
        uint32_t base = sQ + 8192 + s * 16384;
        load64(base, Kg + (size_t)jt * 64 * DHEAD);
        load64(base + 8192, Vg + (size_t)jt * 64 * DHEAD);
        CP_COMMIT();
    };

    load64(sQ, Qg);
    CP_COMMIT();
    load_kv(0, 0);
    CP_WAIT(0);
    __syncthreads();

    int l7 = lane & 7, lg = lane >> 3;
    uint32_t qa[4][4];
#pragma unroll
    for (int ks = 0; ks < 4; ks++) {
        int row = w * 16 + ((lg & 1) << 3) + l7;
        int chunk = ks * 2 + (lg >> 1);
        uint32_t addr = sQ + row * 128 + ((chunk ^ (row & 7)) << 4);
        ldsm_x4(qa[ks][0], qa[ks][1], qa[ks][2], qa[ks][3], addr);
    }

    int quad = lane >> 2, tc2 = (lane & 3) * 2;
    float acc[8][4];
#pragma unroll
    for (int j = 0; j < 8; j++)
#pragma unroll
        for (int v = 0; v < 4; v++) acc[j][v] = 0.f;
    float m0 = -INFINITY, m1 = -INFINITY, l0 = 0.f, l1 = 0.f;

    for (int jt = 0; jt <= qt; jt++) {
        if (jt < qt) { load_kv((jt + 1) & 1, jt + 1); CP_WAIT(1); }
        else         { CP_WAIT(0); }
        __syncthreads();
        uint32_t sK = sQ + 8192 + (jt & 1) * 16384;
        uint32_t sV = sK + 8192;

        float c[8][4];
#pragma unroll
        for (int j = 0; j < 8; j++)
#pragma unroll
            for (int v = 0; v < 4; v++) c[j][v] = 0.f;
#pragma unroll
        for (int ks = 0; ks < 4; ks++) {
            uint32_t kb[4][4];
#pragma unroll
            for (int g = 0; g < 4; g++) {
                int row = g * 16 + (lg >> 1) * 8 + l7;
                int chunk = ks * 2 + (lg & 1);
                uint32_t addr = sK + row * 128 + ((chunk ^ (row & 7)) << 4);
                ldsm_x4(kb[g][0], kb[g][1], kb[g][2], kb[g][3], addr);
            }
#pragma unroll
            for (int j = 0; j < 8; j++)
                mma_bf16(c[j], qa[ks], kb[j >> 1][(j & 1) * 2], kb[j >> 1][(j & 1) * 2 + 1]);
        }

        if (jt == qt) {
            int r0 = w * 16 + quad;
#pragma unroll
            for (int j = 0; j < 8; j++) {
                int kc = j * 8 + tc2;
                if (kc > r0)     c[j][0] = -INFINITY;
                if (kc + 1 > r0) c[j][1] = -INFINITY;
                if (kc > r0 + 8)     c[j][2] = -INFINITY;
                if (kc + 1 > r0 + 8) c[j][3] = -INFINITY;
            }
        }

        float mx0 = -INFINITY, mx1 = -INFINITY;
#pragma unroll
        for (int j = 0; j < 8; j++) {
            mx0 = fmaxf(mx0, fmaxf(c[j][0], c[j][1]));
            mx1 = fmaxf(mx1, fmaxf(c[j][2], c[j][3]));
        }
        mx0 = fmaxf(mx0, __shfl_xor_sync(0xffffffffu, mx0, 1));
        mx0 = fmaxf(mx0, __shfl_xor_sync(0xffffffffu, mx0, 2));
        mx1 = fmaxf(mx1, __shfl_xor_sync(0xffffffffu, mx1, 1));
        mx1 = fmaxf(mx1, __shfl_xor_sync(0xffffffffu, mx1, 2));
        float mn0 = fmaxf(m0, mx0), mn1 = fmaxf(m1, mx1);
        float corr0 = __expf(m0 - mn0), corr1 = __expf(m1 - mn1);
        l0 *= corr0; l1 *= corr1;
#pragma unroll
        for (int j = 0; j < 8; j++) {
            c[j][0] = __expf(c[j][0] - mn0);
            c[j][1] = __expf(c[j][1] - mn0);
            c[j][2] = __expf(c[j][2] - mn1);
            c[j][3] = __expf(c[j][3] - mn1);
            l0 += c[j][0] + c[j][1];
            l1 += c[j][2] + c[j][3];
#pragma unroll
            for (int v = 0; v < 4; v++)
                acc[j][v] *= (v < 2) ? corr0 : corr1;
        }
        m0 = mn0; m1 = mn1;

#pragma unroll
        for (int t = 0; t < 4; t++) {
            uint32_t pa[4];
            pa[0] = pack_bf2(c[2 * t][0], c[2 * t][1]);
            pa[1] = pack_bf2(c[2 * t][2], c[2 * t][3]);
            pa[2] = pack_bf2(c[2 * t + 1][0], c[2 * t + 1][1]);
            pa[3] = pack_bf2(c[2 * t + 1][2], c[2 * t + 1][3]);
#pragma unroll
            for (int nb = 0; nb < 4; nb++) {
                uint32_t vb[4];
                int key = t * 16 + ((lg & 1) << 3) + l7;
                int chunk = nb * 2 + (lg >> 1);
                uint32_t addr = sV + key * 128 + ((chunk ^ (key & 7)) << 4);
                ldsm_x4_trans(vb[0], vb[1], vb[2], vb[3], addr);
                mma_bf16(acc[nb * 2],     pa, vb[0], vb[1]);
                mma_bf16(acc[nb * 2 + 1], pa, vb[2], vb[3]);
            }
        }
        __syncthreads();
    }

    l0 += __shfl_xor_sync(0xffffffffu, l0, 1);
    l0 += __shfl_xor_sync(0xffffffffu, l0, 2);
    l1 += __shfl_xor_sync(0xffffffffu, l1, 1);
    l1 += __shfl_xor_sync(0xffffffffu, l1, 2);
    float inv0 = 1.f / l0, inv1 = 1.f / l1;
    int r0g = b * SEQ + qt * 64 + w * 16 + quad;
#pragma unroll
    for (int j = 0; j < 8; j++) {
        int col = h * 64 + j * 8 + tc2;
        *(uint32_t*)(z + (size_t)r0g * DM + col) = pack_bf2(acc[j][0] * inv0, acc[j][1] * inv0);
        *(uint32_t*)(z + (size_t)(r0g + 8) * DM + col) =
            pack_bf2(acc[j][2] * inv1, acc[j][3] * inv1);
    }
}

// ---------------- launch ----------------
extern "C" void kernel_launch(void* const* d_in, const int* in_sizes, int n_in,
                              void* d_out, int out_size) {
    const float* resid_pre = (const float*)d_in[0];
    const float* W_Q  = (const float*)d_in[1];
    const float* W_K  = (const float*)d_in[2];
    const float* W_V  = (const float*)d_in[3];
    const float* W_O  = (const float*)d_in[4];
    const float* b_Q  = (const float*)d_in[5];
    const float* b_K  = (const float*)d_in[6];
    const float* b_V  = (const float*)d_in[7];
    const float* b_O  = (const float*)d_in[8];
    const float* ln1w = (const float*)d_in[9];
    const float* ln1b = (const float*)d_in[10];
    const float* ln2w = (const float*)d_in[11];
    const float* ln2b = (const float*)d_in[12];
    const float* W_in  = (const float*)d_in[13];
    const float* b_in  = (const float*)d_in[14];
    const float* W_out = (const float*)d_in[15];
    const float* b_out = (const float*)d_in[16];
    float* out = (float*)d_out;

    __nv_bfloat16 *xlnb, *zbf, *wqkv, *wo;
    float *xln, *mid, *hidden, *win, *wout, *bqkv;
    cudaGetSymbolAddress((void**)&xlnb,   g_xln_bf);
    cudaGetSymbolAddress((void**)&xln,    g_xln);
    cudaGetSymbolAddress((void**)&zbf,    g_z_bf);
    cudaGetSymbolAddress((void**)&mid,    g_mid);
    cudaGetSymbolAddress((void**)&hidden, g_hidden);
    cudaGetSymbolAddress((void**)&wqkv,   g_wqkv_bf);
    cudaGetSymbolAddress((void**)&wo,     g_wo_bf);
    cudaGetSymbolAddress((void**)&win,    g_win);
    cudaGetSymbolAddress((void**)&wout,   g_wout);
    cudaGetSymbolAddress((void**)&bqkv,   g_bqkv);

    const int SMEM_BF = 3 * STG_BYTES;   // 96KB
    const int SMEM_TF = 2 * STG_BYTES;   // 64KB -> 2 CTA/SM
    cudaFuncSetAttribute(gemm_bf16_kernel<2>, cudaFuncAttributeMaxDynamicSharedMemorySize, SMEM_BF);
    cudaFuncSetAttribute(gemm_bf16_kernel<3>, cudaFuncAttributeMaxDynamicSharedMemorySize, SMEM_BF);
    cudaFuncSetAttribute(gemm_tf32_kernel<1>, cudaFuncAttributeMaxDynamicSharedMemorySize, SMEM_TF);
    cudaFuncSetAttribute(gemm_tf32_kernel<2>, cudaFuncAttributeMaxDynamicSharedMemorySize, SMEM_TF);

    // weight packing
    pack_wqkv_kernel<<<(QKVN * DM + 255) / 256, 256>>>(W_Q, W_K, W_V, b_Q, b_K, b_V);
    transpose_pack_kernel<1><<<dim3(DM / 32, DM / 32),   dim3(32, 8)>>>(W_O,  wo,   DM,   DM);
    transpose_pack_kernel<0><<<dim3(DMLP / 32, DM / 32), dim3(32, 8)>>>(W_in, win,  DM,   DMLP);
    transpose_pack_kernel<0><<<dim3(DM / 32, DMLP / 32), dim3(32, 8)>>>(W_out, wout, DMLP, DM);

    // 1) LN1 -> bf16
    layernorm_kernel<1><<<ROWS, 256>>>(resid_pre, ln1w, ln1b, xlnb);
    // 2) fused QKV projection (bf16 mma) -> bf16 Q/K/V [b,h,s,d]
    gemm_bf16_kernel<3><<<dim3(QKVN / 128, ROWS / 128), 256, SMEM_BF>>>(xlnb, wqkv, bqkv,
                                                                        nullptr, nullptr, QKVN, DM);
    // 3) tensor-core causal attention -> z (bf16)
    attn_kernel<<<dim3(SEQ / 64, NBH), 128>>>(zbf);
    // 4) O projection (bf16 mma) + bias + residual -> mid (fp32)
    gemm_bf16_kernel<2><<<dim3(DM / 128, ROWS / 128), 256, SMEM_BF>>>(zbf, wo, b_O, resid_pre,
                                                                      mid, DM, DM);
    // 5) LN2 -> tf32 fp32
    layernorm_kernel<0><<<ROWS, 256>>>(mid, ln2w, ln2b, xln);
    // 6) MLP in + bias + GELU (tf32)
    gemm_tf32_kernel<1><<<dim3(DMLP / 128, ROWS / 128), 256, SMEM_TF>>>(xln, win, b_in, nullptr,
                                                                        hidden, DMLP, DM);
    // 7) MLP out + bias + residual -> out (tf32)
    gemm_tf32_kernel<2><<<dim3(DM / 128, ROWS / 128), 256, SMEM_TF>>>(hidden, wout, b_out, mid,
                                                                      out, DM, DMLP);
}

// round 8
// speedup vs baseline: 5.0005x; 1.0238x over previous
#include <cuda_runtime.h>
#include <cuda_bf16.h>
#include <math.h>
#include <stdint.h>

#define ROWS  8192          // B*S
#define DM    768
#define DMLP  3072
#define QKVN  2304
#define NHEAD 12
#define DHEAD 64
#define SEQ   1024
#define NBH   96            // B * NHEAD

// Q pre-scale: 1/sqrt(64) * log2(e)  -> scores land in log2 domain
#define QSCALE 0.1803368801111204f

// ---------------- scratch (device globals; no allocation allowed) ----------------
__device__ __nv_bfloat16 g_xln_bf[ROWS * DM];       // LN1 out (bf16)
__device__ float         g_xln[ROWS * DM];          // LN2 out (tf32-rounded fp32)
__device__ __nv_bfloat16 g_z_bf[ROWS * DM];         // attention out (bf16)
__device__ float         g_mid[ROWS * DM];
__device__ float         g_hidden[ROWS * DMLP];
__device__ __nv_bfloat16 g_wqkv_bf[QKVN * DM];      // [N=2304][K=768] bf16
__device__ __nv_bfloat16 g_wo_bf[DM * DM];          // [N=768][K=768] bf16
__device__ float         g_win[DMLP * DM];          // [N=3072][K=768] tf32
__device__ float         g_wout[DM * DMLP];         // [N=768][K=3072] tf32
__device__ float         g_bqkv[QKVN];
__device__ __nv_bfloat16 g_qbf[NBH * SEQ * DHEAD];  // [b,h,s,d], pre-scaled QSCALE
__device__ __nv_bfloat16 g_kbf[NBH * SEQ * DHEAD];
__device__ __nv_bfloat16 g_vbf[NBH * SEQ * DHEAD];

// ---------------- helpers ----------------
__device__ __forceinline__ uint32_t smem_to_u32(const void* p) {
    uint32_t a;
    asm("{ .reg .u64 t; cvta.to.shared.u64 t, %1; cvt.u32.u64 %0, t; }" : "=r"(a) : "l"(p));
    return a;
}
__device__ __forceinline__ void cp_async16(uint32_t dst, const void* src) {
    asm volatile("cp.async.cg.shared.global [%0], [%1], 16;\n" :: "r"(dst), "l"(src));
}
#define CP_COMMIT() asm volatile("cp.async.commit_group;\n" ::: "memory")
#define CP_WAIT(n)  asm volatile("cp.async.wait_group %0;\n" :: "n"(n) : "memory")

__device__ __forceinline__ void ldsm_x4(uint32_t& r0, uint32_t& r1, uint32_t& r2, uint32_t& r3,
                                        uint32_t addr) {
    asm volatile("ldmatrix.sync.aligned.m8n8.x4.shared.b16 {%0,%1,%2,%3}, [%4];"
                 : "=r"(r0), "=r"(r1), "=r"(r2), "=r"(r3) : "r"(addr));
}
__device__ __forceinline__ void ldsm_x4_trans(uint32_t& r0, uint32_t& r1, uint32_t& r2,
                                              uint32_t& r3, uint32_t addr) {
    asm volatile("ldmatrix.sync.aligned.m8n8.x4.trans.shared.b16 {%0,%1,%2,%3}, [%4];"
                 : "=r"(r0), "=r"(r1), "=r"(r2), "=r"(r3) : "r"(addr));
}
__device__ __forceinline__ void mma_tf32(float* c, const uint32_t* a, uint32_t b0, uint32_t b1) {
    asm volatile(
        "mma.sync.aligned.m16n8k8.row.col.f32.tf32.tf32.f32 "
        "{%0,%1,%2,%3}, {%4,%5,%6,%7}, {%8,%9}, {%0,%1,%2,%3};"
        : "+f"(c[0]), "+f"(c[1]), "+f"(c[2]), "+f"(c[3])
        : "r"(a[0]), "r"(a[1]), "r"(a[2]), "r"(a[3]), "r"(b0), "r"(b1));
}
__device__ __forceinline__ void mma_bf16(float* c, const uint32_t* a, uint32_t b0, uint32_t b1) {
    asm volatile(
        "mma.sync.aligned.m16n8k16.row.col.f32.bf16.bf16.f32 "
        "{%0,%1,%2,%3}, {%4,%5,%6,%7}, {%8,%9}, {%0,%1,%2,%3};"
        : "+f"(c[0]), "+f"(c[1]), "+f"(c[2]), "+f"(c[3])
        : "r"(a[0]), "r"(a[1]), "r"(a[2]), "r"(a[3]), "r"(b0), "r"(b1));
}
__device__ __forceinline__ float to_tf32(float x) {
    uint32_t u;
    asm("cvt.rna.tf32.f32 %0, %1;" : "=r"(u) : "f"(x));
    return __uint_as_float(u);
}
__device__ __forceinline__ uint32_t pack_bf2(float a, float b) {
    __nv_bfloat162 p = __floats2bfloat162_rn(a, b);
    return *(uint32_t*)&p;
}
__device__ __forceinline__ float gelu_new_f(float x) {
    float x3 = x * x * x;
    float t  = tanhf(0.7978845608028654f * (x + 0.044715f * x3));
    return 0.5f * x * (1.0f + t);
}

// ---------------- weight packing ----------------
__global__ void pack_wqkv_kernel(const float* __restrict__ WQ, const float* __restrict__ WK,
                                 const float* __restrict__ WV, const float* __restrict__ bQ,
                                 const float* __restrict__ bK, const float* __restrict__ bV) {
    int idx = blockIdx.x * 256 + threadIdx.x;
    if (idx < QKVN * DM) {
        int j = idx / DM;
        int d = idx - j * DM;
        int which = j / DM;
        int jj = j - which * DM;
        int h = jj >> 6, e = jj & 63;
        const float* W = (which == 0) ? WQ : (which == 1) ? WK : WV;
        g_wqkv_bf[idx] = __float2bfloat16(W[(h * DM + d) * DHEAD + e]);
    }
    if (idx < QKVN) {
        g_bqkv[idx] = (idx < DM) ? bQ[idx] : (idx < 2 * DM) ? bK[idx - DM] : bV[idx - 2 * DM];
    }
}

// in[R][C] fp32 -> out[C][R], OUT=0: tf32-rounded fp32, OUT=1: bf16
template <int OUT>
__global__ void transpose_pack_kernel(const float* __restrict__ in, void* __restrict__ outp,
                                      int R, int C) {
    __shared__ float t[32][33];
    int bx = blockIdx.x * 32, by = blockIdx.y * 32;
    int x = threadIdx.x, y = threadIdx.y;
#pragma unroll
    for (int i = 0; i < 32; i += 8)
        t[y + i][x] = in[(size_t)(by + y + i) * C + bx + x];
    __syncthreads();
#pragma unroll
    for (int i = 0; i < 32; i += 8) {
        size_t di = (size_t)(bx + y + i) * R + by + x;
        if (OUT == 0) ((float*)outp)[di] = to_tf32(t[x][y + i]);
        else          ((__nv_bfloat16*)outp)[di] = __float2bfloat16(t[x][y + i]);
    }
}

// ---------------- LayerNorm, OUT=0: tf32-rounded fp32, OUT=1: bf16 ----------------
template <int OUT>
__global__ void layernorm_kernel(const float* __restrict__ x, const float* __restrict__ w,
                                 const float* __restrict__ b, void* __restrict__ yp) {
    int row = blockIdx.x;
    int tid = threadIdx.x;
    const float* xr = x + (size_t)row * DM;
    float v0 = xr[tid], v1 = xr[tid + 256], v2 = xr[tid + 512];
    float s  = v0 + v1 + v2;
    float ss = v0 * v0 + v1 * v1 + v2 * v2;
#pragma unroll
    for (int o = 16; o > 0; o >>= 1) {
        s  += __shfl_xor_sync(0xffffffffu, s, o);
        ss += __shfl_xor_sync(0xffffffffu, ss, o);
    }
    __shared__ float shs[8], shss[8];
    int warp = tid >> 5, lane = tid & 31;
    if (lane == 0) { shs[warp] = s; shss[warp] = ss; }
    __syncthreads();
    if (tid < 32) {
        s  = (lane < 8) ? shs[lane] : 0.f;
        ss = (lane < 8) ? shss[lane] : 0.f;
#pragma unroll
        for (int o = 4; o > 0; o >>= 1) {
            s  += __shfl_xor_sync(0xffffffffu, s, o);
            ss += __shfl_xor_sync(0xffffffffu, ss, o);
        }
        if (lane == 0) { shs[0] = s; shss[0] = ss; }
    }
    __syncthreads();
    s = shs[0]; ss = shss[0];
    float mean = s * (1.f / DM);
    float var  = ss * (1.f / DM) - mean * mean;
    float rstd = rsqrtf(var + 1e-5f);
    float o0 = (v0 - mean) * rstd * w[tid]       + b[tid];
    float o1 = (v1 - mean) * rstd * w[tid + 256] + b[tid + 256];
    float o2 = (v2 - mean) * rstd * w[tid + 512] + b[tid + 512];
    if (OUT == 0) {
        float* yr = (float*)yp + (size_t)row * DM;
        yr[tid] = to_tf32(o0); yr[tid + 256] = to_tf32(o1); yr[tid + 512] = to_tf32(o2);
    } else {
        __nv_bfloat16* yr = (__nv_bfloat16*)yp + (size_t)row * DM;
        yr[tid] = __float2bfloat16(o0);
        yr[tid + 256] = __float2bfloat16(o1);
        yr[tid + 512] = __float2bfloat16(o2);
    }
}

#define STG_BYTES 32768   // A 16KB + B 16KB per stage

// ---------------- bf16 HMMA GEMM (K=64/stage, 2 stages, 2 CTA/SM) ----------------
// EPI: 2 = fp32 +bias+residual;  3 = QKV split to bf16 g_qbf/g_kbf/g_vbf (Q scaled QSCALE)
template <int EPI>
__global__ __launch_bounds__(256, 2) void gemm_bf16_kernel(
    const __nv_bfloat16* __restrict__ A, const __nv_bfloat16* __restrict__ B,
    const float* __restrict__ bias, const float* __restrict__ Rres,
    float* __restrict__ Cout, int N, int K) {
    extern __shared__ char smem[];
    int tid = threadIdx.x, lane = tid & 31, wid = tid >> 5;
    int bx = blockIdx.x, by = blockIdx.y;
    int warp_m = (wid & 1) * 64;
    int warp_n = (wid >> 1) * 32;

    const __nv_bfloat16* Ab = A + (size_t)(by * 128) * K;
    const __nv_bfloat16* Bb = B + (size_t)(bx * 128) * K;
    uint32_t sbase = smem_to_u32(smem);

    float c[4][4][4];
#pragma unroll
    for (int i = 0; i < 4; i++)
#pragma unroll
        for (int j = 0; j < 4; j++)
#pragma unroll
            for (int k = 0; k < 4; k++) c[i][j][k] = 0.f;

    int T = K >> 6;

    auto load_stage = [&](int s, int kt) {
        uint32_t dstA = sbase + s * STG_BYTES;
        uint32_t dstB = dstA + 16384;
        const __nv_bfloat16* Ag = Ab + kt * 64;
        const __nv_bfloat16* Bg = Bb + kt * 64;
#pragma unroll
        for (int i = 0; i < 4; i++) {
            int idx = tid + i * 256;
            int r = idx >> 3, cc = idx & 7;
            uint32_t off = (uint32_t)(r * 128 + ((cc ^ (r & 7)) * 16));
            cp_async16(dstA + off, Ag + (size_t)r * K + cc * 8);
            cp_async16(dstB + off, Bg + (size_t)r * K + cc * 8);
        }
        CP_COMMIT();
    };

    load_stage(0, 0);
    load_stage(1, 1);

    int l7 = lane & 7;
    int a_r = ((lane >> 3) & 1) * 8 + l7;
    int a_k = lane >> 4;
    int b_r = (lane >> 4) * 8 + l7;
    int b_k = (lane >> 3) & 1;

    for (int t = 0; t < T; t++) {
        if (t + 1 < T) { CP_WAIT(1); } else { CP_WAIT(0); }
        __syncthreads();

        uint32_t sA = sbase + (t & 1) * STG_BYTES;
        uint32_t sB = sA + 16384;
#pragma unroll
        for (int ks = 0; ks < 4; ks++) {
            uint32_t a[4][4];
#pragma unroll
            for (int i = 0; i < 4; i++) {
                int row = warp_m + i * 16 + a_r;
                uint32_t addr = sA + row * 128 + (((ks * 2 + a_k) ^ l7) * 16);
                ldsm_x4(a[i][0], a[i][1], a[i][2], a[i][3], addr);
            }
            uint32_t b[2][4];
#pragma unroll
            for (int j = 0; j < 2; j++) {
                int row = warp_n + j * 16 + b_r;
                uint32_t addr = sB + row * 128 + (((ks * 2 + b_k) ^ l7) * 16);
                ldsm_x4(b[j][0], b[j][1], b[j][2], b[j][3], addr);
            }
#pragma unroll
            for (int i = 0; i < 4; i++)
#pragma unroll
                for (int jj = 0; jj < 4; jj++)
                    mma_bf16(c[i][jj], a[i], b[jj >> 1][(jj & 1) * 2],
                             b[jj >> 1][(jj & 1) * 2 + 1]);
        }
        __syncthreads();
        if (t + 2 < T) load_stage(t & 1, t + 2);
    }

    int quad = lane >> 2, tc2 = (lane & 3) * 2;
#pragma unroll
    for (int i = 0; i < 4; i++) {
#pragma unroll
        for (int jj = 0; jj < 4; jj++) {
            int row0 = by * 128 + warp_m + i * 16 + quad;
            int col  = bx * 128 + warp_n + jj * 8 + tc2;
            float bb0 = bias[col], bb1 = bias[col + 1];
            float v0 = c[i][jj][0] + bb0, v1 = c[i][jj][1] + bb1;
            float v2 = c[i][jj][2] + bb0, v3 = c[i][jj][3] + bb1;
            if (EPI == 3) {
                int which = col / DM;
                int rem = col - which * DM;
                int h = rem >> 6, e = rem & 63;
                __nv_bfloat16* dstb = (which == 0) ? g_qbf : (which == 1) ? g_kbf : g_vbf;
                float sc = (which == 0) ? QSCALE : 1.0f;
#pragma unroll
                for (int rr = 0; rr < 2; rr++) {
                    int rg = row0 + rr * 8;
                    int b_ = rg >> 10, s_ = rg & 1023;
                    size_t di = ((size_t)(b_ * NHEAD + h) * SEQ + s_) * DHEAD + e;
                    float x0 = (rr ? v2 : v0) * sc, x1 = (rr ? v3 : v1) * sc;
                    *(uint32_t*)(dstb + di) = pack_bf2(x0, x1);
                }
            } else {
                const float2 r0 = *(const float2*)(Rres + (size_t)row0 * N + col);
                const float2 r1 = *(const float2*)(Rres + (size_t)(row0 + 8) * N + col);
                v0 += r0.x; v1 += r0.y; v2 += r1.x; v3 += r1.y;
                *(float2*)(Cout + (size_t)row0 * N + col)       = make_float2(v0, v1);
                *(float2*)(Cout + (size_t)(row0 + 8) * N + col) = make_float2(v2, v3);
            }
        }
    }
}

// ---------------- tf32 HMMA GEMM (K=32/stage, 2 stages, 2 CTA/SM) ----------------
// EPI: 1 = fp32 +bias+GELU tf32-rounded;  2 = fp32 +bias+residual
template <int EPI>
__global__ __launch_bounds__(256, 2) void gemm_tf32_kernel(
    const float* __restrict__ A, const float* __restrict__ B,
    const float* __restrict__ bias, const float* __restrict__ Rres,
    float* __restrict__ Cout, int N, int K) {
    extern __shared__ char smem[];
    int tid = threadIdx.x, lane = tid & 31, wid = tid >> 5;
    int bx = blockIdx.x, by = blockIdx.y;
    int warp_m = (wid & 1) * 64;
    int warp_n = (wid >> 1) * 32;

    const float* Ab = A + (size_t)(by * 128) * K;
    const float* Bb = B + (size_t)(bx * 128) * K;
    uint32_t sbase = smem_to_u32(smem);

    float c[4][4][4];
#pragma unroll
    for (int i = 0; i < 4; i++)
#pragma unroll
        for (int j = 0; j < 4; j++)
#pragma unroll
            for (int k = 0; k < 4; k++) c[i][j][k] = 0.f;

    int T = K >> 5;

    auto load_stage = [&](int s, int kt) {
        uint32_t dstA = sbase + s * STG_BYTES;
        uint32_t dstB = dstA + 16384;
        const float* Ag = Ab + kt * 32;
        const float* Bg = Bb + kt * 32;
#pragma unroll
        for (int i = 0; i < 4; i++) {
            int idx = tid + i * 256;
            int r = idx >> 3, cc = idx & 7;
            uint32_t off = (uint32_t)(r * 128 + ((cc ^ (r & 7)) * 16));
            cp_async16(dstA + off, Ag + (size_t)r * K + cc * 4);
            cp_async16(dstB + off, Bg + (size_t)r * K + cc * 4);
        }
        CP_COMMIT();
    };

    load_stage(0, 0);
    load_stage(1, 1);

    int l7 = lane & 7;
    int lg = lane >> 3;

    for (int t = 0; t < T; t++) {
        if (t + 1 < T) { CP_WAIT(1); } else { CP_WAIT(0); }
        __syncthreads();

        uint32_t sA = sbase + (t & 1) * STG_BYTES;
        uint32_t sB = sA + 16384;
#pragma unroll
        for (int ks = 0; ks < 4; ks++) {
            uint32_t a[4][4];
#pragma unroll
            for (int i = 0; i < 4; i++) {
                int row = warp_m + i * 16 + ((lg & 1) << 3) + l7;
                int chunk = ks * 2 + (lg >> 1);
                uint32_t addr = sA + row * 128 + ((chunk ^ (row & 7)) << 4);
                ldsm_x4(a[i][0], a[i][1], a[i][2], a[i][3], addr);
            }
            uint32_t b[2][4];
#pragma unroll
            for (int j = 0; j < 2; j++) {
                int row = warp_n + (j * 2 + (lg >> 1)) * 8 + l7;
                int chunk = ks * 2 + (lg & 1);
                uint32_t addr = sB + row * 128 + ((chunk ^ (row & 7)) << 4);
                ldsm_x4(b[j][0], b[j][1], b[j][2], b[j][3], addr);
            }
#pragma unroll
            for (int i = 0; i < 4; i++)
#pragma unroll
                for (int jn = 0; jn < 4; jn++)
                    mma_tf32(c[i][jn], a[i], b[jn >> 1][(jn & 1) * 2],
                             b[jn >> 1][(jn & 1) * 2 + 1]);
        }
        __syncthreads();
        if (t + 2 < T) load_stage(t & 1, t + 2);
    }

    int quad = lane >> 2, tc2 = (lane & 3) * 2;
#pragma unroll
    for (int i = 0; i < 4; i++) {
#pragma unroll
        for (int jj = 0; jj < 4; jj++) {
            int row0 = by * 128 + warp_m + i * 16 + quad;
            int col  = bx * 128 + warp_n + jj * 8 + tc2;
            float bb0 = bias[col], bb1 = bias[col + 1];
            float v0 = c[i][jj][0] + bb0, v1 = c[i][jj][1] + bb1;
            float v2 = c[i][jj][2] + bb0, v3 = c[i][jj][3] + bb1;
            if (EPI == 1) {
                v0 = to_tf32(gelu_new_f(v0)); v1 = to_tf32(gelu_new_f(v1));
                v2 = to_tf32(gelu_new_f(v2)); v3 = to_tf32(gelu_new_f(v3));
            }
            if (EPI == 2) {
                const float2 r0 = *(const float2*)(Rres + (size_t)row0 * N + col);
                const float2 r1 = *(const float2*)(Rres + (size_t)(row0 + 8) * N + col);
                v0 += r0.x; v1 += r0.y; v2 += r1.x; v3 += r1.y;
            }
            *(float2*)(Cout + (size_t)row0 * N + col)       = make_float2(v0, v1);
            *(float2*)(Cout + (size_t)(row0 + 8) * N + col) = make_float2(v2, v3);
        }
    }
}

// ---------------- FA2 bf16 attention: 128-row q-tiles, log2-domain softmax ----------------
// grid = (8 q-tiles of 128 rows, 96 b*h). 256 threads = 8 warps x 16 q-rows.
// Scores arrive in log2 units (Q pre-scaled by QSCALE); softmax uses exp2f.
// Warps fully above the causal diagonal skip the tile body.
__global__ __launch_bounds__(256) void attn_kernel(__nv_bfloat16* __restrict__ z) {
    extern __shared__ char sm[];                 // Q 16KB | {K 8KB, V 8KB} x2 stages
    int qt = blockIdx.x;
    int bh = blockIdx.y;
    int b = bh / NHEAD, h = bh - b * NHEAD;
    int tid = threadIdx.x, lane = tid & 31, w = tid >> 5;

    uint32_t sQ = smem_to_u32(sm);
    const __nv_bfloat16* Qg = g_qbf + ((size_t)bh * SEQ + qt * 128) * DHEAD;
    const __nv_bfloat16* Kg = g_kbf + (size_t)bh * SEQ * DHEAD;
    const __nv_bfloat16* Vg = g_vbf + (size_t)bh * SEQ * DHEAD;

    // Q: 128 rows (1024 16B-chunks), KV: 64 rows (512 chunks) each
    {
#pragma unroll
        for (int i = 0; i < 4; i++) {
            int idx = tid + i * 256;
            int r = idx >> 3, cc = idx & 7;
            uint32_t off = (uint32_t)(r * 128 + ((cc ^ (r & 7)) << 4));
            cp_async16(sQ + off, Qg + (size_t)r * DHEAD + cc * 8);
        }
        CP_COMMIT();
    }
    auto load_kv = [&](int s, int jt) {
        uint32_t bK = sQ + 16384 + s * 16384;
        const __nv_bfloat16* Ksrc = Kg + (size_t)jt * 64 * DHEAD;
        const __nv_bfloat16* Vsrc = Vg + (size_t)jt * 64 * DHEAD;
#pragma unroll
        for (int i = 0; i < 2; i++) {
            int idx = tid + i * 256;
            int r = idx >> 3, cc = idx & 7;
            uint32_t off = (uint32_t)(r * 128 + ((cc ^ (r & 7)) << 4));
            cp_async16(bK + off, Ksrc + (size_t)r * DHEAD + cc * 8);
            cp_async16(bK + 8192 + off, Vsrc + (size_t)r * DHEAD + cc * 8);
        }
        CP_COMMIT();
    };

    load_kv(0, 0);
    CP_WAIT(0);
    __syncthreads();

    int l7 = lane & 7, lg = lane >> 3;
    uint32_t qa[4][4];
#pragma unroll
    for (int ks = 0; ks < 4; ks++) {
        int row = w * 16 + ((lg & 1) << 3) + l7;
        int chunk = ks * 2 + (lg >> 1);
        uint32_t addr = sQ + row * 128 + ((chunk ^ (row & 7)) << 4);
        ldsm_x4(qa[ks][0], qa[ks][1], qa[ks][2], qa[ks][3], addr);
    }

    int quad = lane >> 2, tc2 = (lane & 3) * 2;
    int wrow = qt * 128 + w * 16;                // this warp's first q-row (global)
    float acc[8][4];
#pragma unroll
    for (int j = 0; j < 8; j++)
#pragma unroll
        for (int v = 0; v < 4; v++) acc[j][v] = 0.f;
    float m0 = -INFINITY, m1 = -INFINITY, l0 = 0.f, l1 = 0.f;

    int ntile = 2 * qt + 2;
    for (int jt = 0; jt < ntile; jt++) {
        if (jt + 1 < ntile) { load_kv((jt + 1) & 1, jt + 1); CP_WAIT(1); }
        else                { CP_WAIT(0); }
        __syncthreads();

        if (jt * 64 <= wrow + 15) {              // warp has unmasked keys in this tile
            uint32_t sK = sQ + 16384 + (jt & 1) * 16384;
            uint32_t sV = sK + 8192;

            float c[8][4];
#pragma unroll
            for (int j = 0; j < 8; j++)
#pragma unroll
                for (int v = 0; v < 4; v++) c[j][v] = 0.f;
#pragma unroll
            for (int ks = 0; ks < 4; ks++) {
                uint32_t kb[4][4];
#pragma unroll
                for (int g = 0; g < 4; g++) {
                    int row = g * 16 + (lg >> 1) * 8 + l7;
                    int chunk = ks * 2 + (lg & 1);
                    uint32_t addr = sK + row * 128 + ((chunk ^ (row & 7)) << 4);
                    ldsm_x4(kb[g][0], kb[g][1], kb[g][2], kb[g][3], addr);
                }
#pragma unroll
                for (int j = 0; j < 8; j++)
                    mma_bf16(c[j], qa[ks], kb[j >> 1][(j & 1) * 2],
                             kb[j >> 1][(j & 1) * 2 + 1]);
            }

            if ((jt + 1) * 64 - 1 > wrow) {      // partial (diagonal) tile for this warp
                int r0 = wrow + quad;
                int kbase = jt * 64;
#pragma unroll
                for (int j = 0; j < 8; j++) {
                    int kc = kbase + j * 8 + tc2;
                    if (kc > r0)     c[j][0] = -INFINITY;
                    if (kc + 1 > r0) c[j][1] = -INFINITY;
                    if (kc > r0 + 8)     c[j][2] = -INFINITY;
                    if (kc + 1 > r0 + 8) c[j][3] = -INFINITY;
                }
            }

            float mx0 = -INFINITY, mx1 = -INFINITY;
#pragma unroll
            for (int j = 0; j < 8; j++) {
                mx0 = fmaxf(mx0, fmaxf(c[j][0], c[j][1]));
                mx1 = fmaxf(mx1, fmaxf(c[j][2], c[j][3]));
            }
            mx0 = fmaxf(mx0, __shfl_xor_sync(0xffffffffu, mx0, 1));
            mx0 = fmaxf(mx0, __shfl_xor_sync(0xffffffffu, mx0, 2));
            mx1 = fmaxf(mx1, __shfl_xor_sync(0xffffffffu, mx1, 1));
            mx1 = fmaxf(mx1, __shfl_xor_sync(0xffffffffu, mx1, 2));
            float mn0 = fmaxf(m0, mx0), mn1 = fmaxf(m1, mx1);
            float corr0 = exp2f(m0 - mn0), corr1 = exp2f(m1 - mn1);
            l0 *= corr0; l1 *= corr1;
#pragma unroll
            for (int j = 0; j < 8; j++) {
                c[j][0] = exp2f(c[j][0] - mn0);
                c[j][1] = exp2f(c[j][1] - mn0);
                c[j][2] = exp2f(c[j][2] - mn1);
                c[j][3] = exp2f(c[j][3] - mn1);
                l0 += c[j][0] + c[j][1];
                l1 += c[j][2] + c[j][3];
#pragma unroll
                for (int v = 0; v < 4; v++)
                    acc[j][v] *= (v < 2) ? corr0 : corr1;
            }
            m0 = mn0; m1 = mn1;

#pragma unroll
            for (int t = 0; t < 4; t++) {
                uint32_t pa[4];
                pa[0] = pack_bf2(c[2 * t][0], c[2 * t][1]);
                pa[1] = pack_bf2(c[2 * t][2], c[2 * t][3]);
                pa[2] = pack_bf2(c[2 * t + 1][0], c[2 * t + 1][1]);
                pa[3] = pack_bf2(c[2 * t + 1][2], c[2 * t + 1][3]);
#pragma unroll
                for (int nb = 0; nb < 4; nb++) {
                    uint32_t vb[4];
                    int key = t * 16 + ((lg & 1) << 3) + l7;
                    int chunk = nb * 2 + (lg >> 1);
                    uint32_t addr = sV + key * 128 + ((chunk ^ (key & 7)) << 4);
                    ldsm_x4_trans(vb[0], vb[1], vb[2], vb[3], addr);
                    mma_bf16(acc[nb * 2],     pa, vb[0], vb[1]);
                    mma_bf16(acc[nb * 2 + 1], pa, vb[2], vb[3]);
                }
            }
        }
        __syncthreads();
    }

    l0 += __shfl_xor_sync(0xffffffffu, l0, 1);
    l0 += __shfl_xor_sync(0xffffffffu, l0, 2);
    l1 += __shfl_xor_sync(0xffffffffu, l1, 1);
    l1 += __shfl_xor_sync(0xffffffffu, l1, 2);
    float inv0 = 1.f / l0, inv1 = 1.f / l1;
    int r0g = b * SEQ + qt * 128 + w * 16 + quad;
#pragma unroll
    for (int j = 0; j < 8; j++) {
        int col = h * 64 + j * 8 + tc2;
        *(uint32_t*)(z + (size_t)r0g * DM + col) = pack_bf2(acc[j][0] * inv0, acc[j][1] * inv0);
        *(uint32_t*)(z + (size_t)(r0g + 8) * DM + col) =
            pack_bf2(acc[j][2] * inv1, acc[j][3] * inv1);
    }
}

// ---------------- launch ----------------
extern "C" void kernel_launch(void* const* d_in, const int* in_sizes, int n_in,
                              void* d_out, int out_size) {
    const float* resid_pre = (const float*)d_in[0];
    const float* W_Q  = (const float*)d_in[1];
    const float* W_K  = (const float*)d_in[2];
    const float* W_V  = (const float*)d_in[3];
    const float* W_O  = (const float*)d_in[4];
    const float* b_Q  = (const float*)d_in[5];
    const float* b_K  = (const float*)d_in[6];
    const float* b_V  = (const float*)d_in[7];
    const float* b_O  = (const float*)d_in[8];
    const float* ln1w = (const float*)d_in[9];
    const float* ln1b = (const float*)d_in[10];
    const float* ln2w = (const float*)d_in[11];
    const float* ln2b = (const float*)d_in[12];
    const float* W_in  = (const float*)d_in[13];
    const float* b_in  = (const float*)d_in[14];
    const float* W_out = (const float*)d_in[15];
    const float* b_out = (const float*)d_in[16];
    float* out = (float*)d_out;

    __nv_bfloat16 *xlnb, *zbf, *wqkv, *wo;
    float *xln, *mid, *hidden, *win, *wout, *bqkv;
    cudaGetSymbolAddress((void**)&xlnb,   g_xln_bf);
    cudaGetSymbolAddress((void**)&xln,    g_xln);
    cudaGetSymbolAddress((void**)&zbf,    g_z_bf);
    cudaGetSymbolAddress((void**)&mid,    g_mid);
    cudaGetSymbolAddress((void**)&hidden, g_hidden);
    cudaGetSymbolAddress((void**)&wqkv,   g_wqkv_bf);
    cudaGetSymbolAddress((void**)&wo,     g_wo_bf);
    cudaGetSymbolAddress((void**)&win,    g_win);
    cudaGetSymbolAddress((void**)&wout,   g_wout);
    cudaGetSymbolAddress((void**)&bqkv,   g_bqkv);

    const int SMEM_G = 2 * STG_BYTES;           // 64KB, 2 CTA/SM
    const int SMEM_A = 16384 + 2 * 16384;       // 48KB attention
    cudaFuncSetAttribute(gemm_bf16_kernel<2>, cudaFuncAttributeMaxDynamicSharedMemorySize, SMEM_G);
    cudaFuncSetAttribute(gemm_bf16_kernel<3>, cudaFuncAttributeMaxDynamicSharedMemorySize, SMEM_G);
    cudaFuncSetAttribute(gemm_tf32_kernel<1>, cudaFuncAttributeMaxDynamicSharedMemorySize, SMEM_G);
    cudaFuncSetAttribute(gemm_tf32_kernel<2>, cudaFuncAttributeMaxDynamicSharedMemorySize, SMEM_G);
    cudaFuncSetAttribute(attn_kernel, cudaFuncAttributeMaxDynamicSharedMemorySize, SMEM_A);

    // weight packing
    pack_wqkv_kernel<<<(QKVN * DM + 255) / 256, 256>>>(W_Q, W_K, W_V, b_Q, b_K, b_V);
    transpose_pack_kernel<1><<<dim3(DM / 32, DM / 32),   dim3(32, 8)>>>(W_O,  wo,   DM,   DM);
    transpose_pack_kernel<0><<<dim3(DMLP / 32, DM / 32), dim3(32, 8)>>>(W_in, win,  DM,   DMLP);
    transpose_pack_kernel<0><<<dim3(DM / 32, DMLP / 32), dim3(32, 8)>>>(W_out, wout, DMLP, DM);

    // 1) LN1 -> bf16
    layernorm_kernel<1><<<ROWS, 256>>>(resid_pre, ln1w, ln1b, xlnb);
    // 2) fused QKV projection (bf16 mma) -> bf16 Q/K/V [b,h,s,d], Q in log2-softmax scale
    gemm_bf16_kernel<3><<<dim3(QKVN / 128, ROWS / 128), 256, SMEM_G>>>(xlnb, wqkv, bqkv,
                                                                       nullptr, nullptr, QKVN, DM);
    // 3) tensor-core causal attention -> z (bf16)
    attn_kernel<<<dim3(SEQ / 128, NBH), 256, SMEM_A>>>(zbf);
    // 4) O projection (bf16 mma) + bias + residual -> mid (fp32)
    gemm_bf16_kernel<2><<<dim3(DM / 128, ROWS / 128), 256, SMEM_G>>>(zbf, wo, b_O, resid_pre,
                                                                     mid, DM, DM);
    // 5) LN2 -> tf32 fp32
    layernorm_kernel<0><<<ROWS, 256>>>(mid, ln2w, ln2b, xln);
    // 6) MLP in + bias + GELU (tf32)
    gemm_tf32_kernel<1><<<dim3(DMLP / 128, ROWS / 128), 256, SMEM_G>>>(xln, win, b_in, nullptr,
                                                                       hidden, DMLP, DM);
    // 7) MLP out + bias + residual -> out (tf32)
    gemm_tf32_kernel<2><<<dim3(DM / 128, ROWS / 128), 256, SMEM_G>>>(hidden, wout, b_out, mid,
                                                                     out, DM, DMLP);
}

// round 9
// speedup vs baseline: 7.0000x; 1.3999x over previous
#include <cuda_runtime.h>
#include <cuda_fp16.h>
#include <math.h>
#include <stdint.h>

#define ROWS  8192          // B*S
#define DM    768
#define DMLP  3072
#define QKVN  2304
#define NHEAD 12
#define DHEAD 64
#define SEQ   1024
#define NBH   96            // B * NHEAD

// Q pre-scale: 1/sqrt(64) * log2(e)  -> scores land in log2 domain
#define QSCALE 0.1803368801111204f

// ---------------- scratch (device globals; no allocation allowed) ----------------
__device__ __half g_x16[ROWS * DM];          // LN1 / LN2 out (fp16, reused sequentially)
__device__ __half g_z16[ROWS * DM];          // attention out (fp16)
__device__ float  g_mid[ROWS * DM];
__device__ __half g_h16[ROWS * DMLP];        // MLP hidden (fp16)
__device__ __half g_wqkv[QKVN * DM];         // [N=2304][K=768] fp16
__device__ __half g_wo[DM * DM];             // [N=768][K=768] fp16
__device__ __half g_win[DMLP * DM];          // [N=3072][K=768] fp16
__device__ __half g_wout[DM * DMLP];         // [N=768][K=3072] fp16
__device__ float  g_bqkv[QKVN];
__device__ __half g_q16[NBH * SEQ * DHEAD];  // [b,h,s,d], pre-scaled QSCALE
__device__ __half g_k16[NBH * SEQ * DHEAD];
__device__ __half g_v16[NBH * SEQ * DHEAD];

// ---------------- helpers ----------------
__device__ __forceinline__ uint32_t smem_to_u32(const void* p) {
    uint32_t a;
    asm("{ .reg .u64 t; cvta.to.shared.u64 t, %1; cvt.u32.u64 %0, t; }" : "=r"(a) : "l"(p));
    return a;
}
__device__ __forceinline__ void cp_async16(uint32_t dst, const void* src) {
    asm volatile("cp.async.cg.shared.global [%0], [%1], 16;\n" :: "r"(dst), "l"(src));
}
#define CP_COMMIT() asm volatile("cp.async.commit_group;\n" ::: "memory")
#define CP_WAIT(n)  asm volatile("cp.async.wait_group %0;\n" :: "n"(n) : "memory")

__device__ __forceinline__ void ldsm_x4(uint32_t& r0, uint32_t& r1, uint32_t& r2, uint32_t& r3,
                                        uint32_t addr) {
    asm volatile("ldmatrix.sync.aligned.m8n8.x4.shared.b16 {%0,%1,%2,%3}, [%4];"
                 : "=r"(r0), "=r"(r1), "=r"(r2), "=r"(r3) : "r"(addr));
}
__device__ __forceinline__ void ldsm_x4_trans(uint32_t& r0, uint32_t& r1, uint32_t& r2,
                                              uint32_t& r3, uint32_t addr) {
    asm volatile("ldmatrix.sync.aligned.m8n8.x4.trans.shared.b16 {%0,%1,%2,%3}, [%4];"
                 : "=r"(r0), "=r"(r1), "=r"(r2), "=r"(r3) : "r"(addr));
}
__device__ __forceinline__ void mma_f16(float* c, const uint32_t* a, uint32_t b0, uint32_t b1) {
    asm volatile(
        "mma.sync.aligned.m16n8k16.row.col.f32.f16.f16.f32 "
        "{%0,%1,%2,%3}, {%4,%5,%6,%7}, {%8,%9}, {%0,%1,%2,%3};"
        : "+f"(c[0]), "+f"(c[1]), "+f"(c[2]), "+f"(c[3])
        : "r"(a[0]), "r"(a[1]), "r"(a[2]), "r"(a[3]), "r"(b0), "r"(b1));
}
__device__ __forceinline__ uint32_t pack_h2(float a, float b) {
    __half2 p = __floats2half2_rn(a, b);
    return *(uint32_t*)&p;
}
__device__ __forceinline__ float gelu_new_f(float x) {
    float x3 = x * x * x;
    float t  = tanhf(0.7978845608028654f * (x + 0.044715f * x3));
    return 0.5f * x * (1.0f + t);
}

// ---------------- weight packing ----------------
__global__ void pack_wqkv_kernel(const float* __restrict__ WQ, const float* __restrict__ WK,
                                 const float* __restrict__ WV, const float* __restrict__ bQ,
                                 const float* __restrict__ bK, const float* __restrict__ bV) {
    int idx = blockIdx.x * 256 + threadIdx.x;
    if (idx < QKVN * DM) {
        int j = idx / DM;
        int d = idx - j * DM;
        int which = j / DM;
        int jj = j - which * DM;
        int h = jj >> 6, e = jj & 63;
        const float* W = (which == 0) ? WQ : (which == 1) ? WK : WV;
        g_wqkv[idx] = __float2half(W[(h * DM + d) * DHEAD + e]);
    }
    if (idx < QKVN) {
        g_bqkv[idx] = (idx < DM) ? bQ[idx] : (idx < 2 * DM) ? bK[idx - DM] : bV[idx - 2 * DM];
    }
}

// in[R][C] fp32 -> out[C][R] fp16
__global__ void transpose_pack_kernel(const float* __restrict__ in, __half* __restrict__ outp,
                                      int R, int C) {
    __shared__ float t[32][33];
    int bx = blockIdx.x * 32, by = blockIdx.y * 32;
    int x = threadIdx.x, y = threadIdx.y;
#pragma unroll
    for (int i = 0; i < 32; i += 8)
        t[y + i][x] = in[(size_t)(by + y + i) * C + bx + x];
    __syncthreads();
#pragma unroll
    for (int i = 0; i < 32; i += 8)
        outp[(size_t)(bx + y + i) * R + by + x] = __float2half(t[x][y + i]);
}

// ---------------- LayerNorm (emits fp16) ----------------
__global__ void layernorm_kernel(const float* __restrict__ x, const float* __restrict__ w,
                                 const float* __restrict__ b, __half* __restrict__ yp) {
    int row = blockIdx.x;
    int tid = threadIdx.x;
    const float* xr = x + (size_t)row * DM;
    float v0 = xr[tid], v1 = xr[tid + 256], v2 = xr[tid + 512];
    float s  = v0 + v1 + v2;
    float ss = v0 * v0 + v1 * v1 + v2 * v2;
#pragma unroll
    for (int o = 16; o > 0; o >>= 1) {
        s  += __shfl_xor_sync(0xffffffffu, s, o);
        ss += __shfl_xor_sync(0xffffffffu, ss, o);
    }
    __shared__ float shs[8], shss[8];
    int warp = tid >> 5, lane = tid & 31;
    if (lane == 0) { shs[warp] = s; shss[warp] = ss; }
    __syncthreads();
    if (tid < 32) {
        s  = (lane < 8) ? shs[lane] : 0.f;
        ss = (lane < 8) ? shss[lane] : 0.f;
#pragma unroll
        for (int o = 4; o > 0; o >>= 1) {
            s  += __shfl_xor_sync(0xffffffffu, s, o);
            ss += __shfl_xor_sync(0xffffffffu, ss, o);
        }
        if (lane == 0) { shs[0] = s; shss[0] = ss; }
    }
    __syncthreads();
    s = shs[0]; ss = shss[0];
    float mean = s * (1.f / DM);
    float var  = ss * (1.f / DM) - mean * mean;
    float rstd = rsqrtf(var + 1e-5f);
    __half* yr = yp + (size_t)row * DM;
    yr[tid]       = __float2half((v0 - mean) * rstd * w[tid]       + b[tid]);
    yr[tid + 256] = __float2half((v1 - mean) * rstd * w[tid + 256] + b[tid + 256]);
    yr[tid + 512] = __float2half((v2 - mean) * rstd * w[tid + 512] + b[tid + 512]);
}

#define STG_BYTES 32768   // A 16KB + B 16KB per stage (K=64 fp16)

// ---------------- fp16 HMMA GEMM: C[M,N] = A[M,K] x B[N,K]^T (K=64/stage, 2 stages) ----
// EPI: 1 = fp16 out +bias+GELU;  2 = fp32 out +bias+residual;
//      3 = QKV split to fp16 g_q16/g_k16/g_v16 (Q scaled QSCALE)
template <int EPI>
__global__ __launch_bounds__(256, 2) void gemm_f16_kernel(
    const __half* __restrict__ A, const __half* __restrict__ B,
    const float* __restrict__ bias, const float* __restrict__ Rres,
    void* __restrict__ Cout, int N, int K) {
    extern __shared__ char smem[];
    int tid = threadIdx.x, lane = tid & 31, wid = tid >> 5;
    int bx = blockIdx.x, by = blockIdx.y;
    int warp_m = (wid & 1) * 64;
    int warp_n = (wid >> 1) * 32;

    const __half* Ab = A + (size_t)(by * 128) * K;
    const __half* Bb = B + (size_t)(bx * 128) * K;
    uint32_t sbase = smem_to_u32(smem);

    float c[4][4][4];
#pragma unroll
    for (int i = 0; i < 4; i++)
#pragma unroll
        for (int j = 0; j < 4; j++)
#pragma unroll
            for (int k = 0; k < 4; k++) c[i][j][k] = 0.f;

    int T = K >> 6;

    auto load_stage = [&](int s, int kt) {
        uint32_t dstA = sbase + s * STG_BYTES;
        uint32_t dstB = dstA + 16384;
        const __half* Ag = Ab + kt * 64;
        const __half* Bg = Bb + kt * 64;
#pragma unroll
        for (int i = 0; i < 4; i++) {
            int idx = tid + i * 256;
            int r = idx >> 3, cc = idx & 7;
            uint32_t off = (uint32_t)(r * 128 + ((cc ^ (r & 7)) * 16));
            cp_async16(dstA + off, Ag + (size_t)r * K + cc * 8);
            cp_async16(dstB + off, Bg + (size_t)r * K + cc * 8);
        }
        CP_COMMIT();
    };

    load_stage(0, 0);
    load_stage(1, 1);

    int l7 = lane & 7;
    int a_r = ((lane >> 3) & 1) * 8 + l7;
    int a_k = lane >> 4;
    int b_r = (lane >> 4) * 8 + l7;
    int b_k = (lane >> 3) & 1;

    for (int t = 0; t < T; t++) {
        if (t + 1 < T) { CP_WAIT(1); } else { CP_WAIT(0); }
        __syncthreads();

        uint32_t sA = sbase + (t & 1) * STG_BYTES;
        uint32_t sB = sA + 16384;
#pragma unroll
        for (int ks = 0; ks < 4; ks++) {
            uint32_t a[4][4];
#pragma unroll
            for (int i = 0; i < 4; i++) {
                int row = warp_m + i * 16 + a_r;
                uint32_t addr = sA + row * 128 + (((ks * 2 + a_k) ^ l7) * 16);
                ldsm_x4(a[i][0], a[i][1], a[i][2], a[i][3], addr);
            }
            uint32_t b[2][4];
#pragma unroll
            for (int j = 0; j < 2; j++) {
                int row = warp_n + j * 16 + b_r;
                uint32_t addr = sB + row * 128 + (((ks * 2 + b_k) ^ l7) * 16);
                ldsm_x4(b[j][0], b[j][1], b[j][2], b[j][3], addr);
            }
#pragma unroll
            for (int i = 0; i < 4; i++)
#pragma unroll
                for (int jj = 0; jj < 4; jj++)
                    mma_f16(c[i][jj], a[i], b[jj >> 1][(jj & 1) * 2],
                            b[jj >> 1][(jj & 1) * 2 + 1]);
        }
        __syncthreads();
        if (t + 2 < T) load_stage(t & 1, t + 2);
    }

    int quad = lane >> 2, tc2 = (lane & 3) * 2;
#pragma unroll
    for (int i = 0; i < 4; i++) {
#pragma unroll
        for (int jj = 0; jj < 4; jj++) {
            int row0 = by * 128 + warp_m + i * 16 + quad;
            int col  = bx * 128 + warp_n + jj * 8 + tc2;
            float bb0 = bias[col], bb1 = bias[col + 1];
            float v0 = c[i][jj][0] + bb0, v1 = c[i][jj][1] + bb1;
            float v2 = c[i][jj][2] + bb0, v3 = c[i][jj][3] + bb1;
            if (EPI == 3) {
                int which = col / DM;
                int rem = col - which * DM;
                int h = rem >> 6, e = rem & 63;
                __half* dsth = (which == 0) ? g_q16 : (which == 1) ? g_k16 : g_v16;
                float sc = (which == 0) ? QSCALE : 1.0f;
#pragma unroll
                for (int rr = 0; rr < 2; rr++) {
                    int rg = row0 + rr * 8;
                    int b_ = rg >> 10, s_ = rg & 1023;
                    size_t di = ((size_t)(b_ * NHEAD + h) * SEQ + s_) * DHEAD + e;
                    float x0 = (rr ? v2 : v0) * sc, x1 = (rr ? v3 : v1) * sc;
                    *(uint32_t*)(dsth + di) = pack_h2(x0, x1);
                }
            } else if (EPI == 1) {
                v0 = gelu_new_f(v0); v1 = gelu_new_f(v1);
                v2 = gelu_new_f(v2); v3 = gelu_new_f(v3);
                __half* Ch = (__half*)Cout;
                *(uint32_t*)(Ch + (size_t)row0 * N + col)       = pack_h2(v0, v1);
                *(uint32_t*)(Ch + (size_t)(row0 + 8) * N + col) = pack_h2(v2, v3);
            } else {
                const float2 r0 = *(const float2*)(Rres + (size_t)row0 * N + col);
                const float2 r1 = *(const float2*)(Rres + (size_t)(row0 + 8) * N + col);
                v0 += r0.x; v1 += r0.y; v2 += r1.x; v3 += r1.y;
                float* Cf = (float*)Cout;
                *(float2*)(Cf + (size_t)row0 * N + col)       = make_float2(v0, v1);
                *(float2*)(Cf + (size_t)(row0 + 8) * N + col) = make_float2(v2, v3);
            }
        }
    }
}

// ---------------- FA2 fp16 attention: 128-row q-tiles, log2-domain softmax ----------------
__global__ __launch_bounds__(256) void attn_kernel(__half* __restrict__ z) {
    extern __shared__ char sm[];                 // Q 16KB | {K 8KB, V 8KB} x2 stages
    int qt = blockIdx.x;
    int bh = blockIdx.y;
    int b = bh / NHEAD, h = bh - b * NHEAD;
    int tid = threadIdx.x, lane = tid & 31, w = tid >> 5;

    uint32_t sQ = smem_to_u32(sm);
    const __half* Qg = g_q16 + ((size_t)bh * SEQ + qt * 128) * DHEAD;
    const __half* Kg = g_k16 + (size_t)bh * SEQ * DHEAD;
    const __half* Vg = g_v16 + (size_t)bh * SEQ * DHEAD;

    {
#pragma unroll
        for (int i = 0; i < 4; i++) {
            int idx = tid + i * 256;
            int r = idx >> 3, cc = idx & 7;
            uint32_t off = (uint32_t)(r * 128 + ((cc ^ (r & 7)) << 4));
            cp_async16(sQ + off, Qg + (size_t)r * DHEAD + cc * 8);
        }
        CP_COMMIT();
    }
    auto load_kv = [&](int s, int jt) {
        uint32_t bK = sQ + 16384 + s * 16384;
        const __half* Ksrc = Kg + (size_t)jt * 64 * DHEAD;
        const __half* Vsrc = Vg + (size_t)jt * 64 * DHEAD;
#pragma unroll
        for (int i = 0; i < 2; i++) {
            int idx = tid + i * 256;
            int r = idx >> 3, cc = idx & 7;
            uint32_t off = (uint32_t)(r * 128 + ((cc ^ (r & 7)) << 4));
            cp_async16(bK + off, Ksrc + (size_t)r * DHEAD + cc * 8);
            cp_async16(bK + 8192 + off, Vsrc + (size_t)r * DHEAD + cc * 8);
        }
        CP_COMMIT();
    };

    load_kv(0, 0);
    CP_WAIT(0);
    __syncthreads();

    int l7 = lane & 7, lg = lane >> 3;
    uint32_t qa[4][4];
#pragma unroll
    for (int ks = 0; ks < 4; ks++) {
        int row = w * 16 + ((lg & 1) << 3) + l7;
        int chunk = ks * 2 + (lg >> 1);
        uint32_t addr = sQ + row * 128 + ((chunk ^ (row & 7)) << 4);
        ldsm_x4(qa[ks][0], qa[ks][1], qa[ks][2], qa[ks][3], addr);
    }

    int quad = lane >> 2, tc2 = (lane & 3) * 2;
    int wrow = qt * 128 + w * 16;
    float acc[8][4];
#pragma unroll
    for (int j = 0; j < 8; j++)
#pragma unroll
        for (int v = 0; v < 4; v++) acc[j][v] = 0.f;
    float m0 = -INFINITY, m1 = -INFINITY, l0 = 0.f, l1 = 0.f;

    int ntile = 2 * qt + 2;
    for (int jt = 0; jt < ntile; jt++) {
        if (jt + 1 < ntile) { load_kv((jt + 1) & 1, jt + 1); CP_WAIT(1); }
        else                { CP_WAIT(0); }
        __syncthreads();

        if (jt * 64 <= wrow + 15) {
            uint32_t sK = sQ + 16384 + (jt & 1) * 16384;
            uint32_t sV = sK + 8192;

            float c[8][4];
#pragma unroll
            for (int j = 0; j < 8; j++)
#pragma unroll
                for (int v = 0; v < 4; v++) c[j][v] = 0.f;
#pragma unroll
            for (int ks = 0; ks < 4; ks++) {
                uint32_t kb[4][4];
#pragma unroll
                for (int g = 0; g < 4; g++) {
                    int row = g * 16 + (lg >> 1) * 8 + l7;
                    int chunk = ks * 2 + (lg & 1);
                    uint32_t addr = sK + row * 128 + ((chunk ^ (row & 7)) << 4);
                    ldsm_x4(kb[g][0], kb[g][1], kb[g][2], kb[g][3], addr);
                }
#pragma unroll
                for (int j = 0; j < 8; j++)
                    mma_f16(c[j], qa[ks], kb[j >> 1][(j & 1) * 2],
                            kb[j >> 1][(j & 1) * 2 + 1]);
            }

            if ((jt + 1) * 64 - 1 > wrow) {
                int r0 = wrow + quad;
                int kbase = jt * 64;
#pragma unroll
                for (int j = 0; j < 8; j++) {
                    int kc = kbase + j * 8 + tc2;
                    if (kc > r0)     c[j][0] = -INFINITY;
                    if (kc + 1 > r0) c[j][1] = -INFINITY;
                    if (kc > r0 + 8)     c[j][2] = -INFINITY;
                    if (kc + 1 > r0 + 8) c[j][3] = -INFINITY;
                }
            }

            float mx0 = -INFINITY, mx1 = -INFINITY;
#pragma unroll
            for (int j = 0; j < 8; j++) {
                mx0 = fmaxf(mx0, fmaxf(c[j][0], c[j][1]));
                mx1 = fmaxf(mx1, fmaxf(c[j][2], c[j][3]));
            }
            mx0 = fmaxf(mx0, __shfl_xor_sync(0xffffffffu, mx0, 1));
            mx0 = fmaxf(mx0, __shfl_xor_sync(0xffffffffu, mx0, 2));
            mx1 = fmaxf(mx1, __shfl_xor_sync(0xffffffffu, mx1, 1));
            mx1 = fmaxf(mx1, __shfl_xor_sync(0xffffffffu, mx1, 2));
            float mn0 = fmaxf(m0, mx0), mn1 = fmaxf(m1, mx1);
            float corr0 = exp2f(m0 - mn0), corr1 = exp2f(m1 - mn1);
            l0 *= corr0; l1 *= corr1;
#pragma unroll
            for (int j = 0; j < 8; j++) {
                c[j][0] = exp2f(c[j][0] - mn0);
                c[j][1] = exp2f(c[j][1] - mn0);
                c[j][2] = exp2f(c[j][2] - mn1);
                c[j][3] = exp2f(c[j][3] - mn1);
                l0 += c[j][0] + c[j][1];
                l1 += c[j][2] + c[j][3];
#pragma unroll
                for (int v = 0; v < 4; v++)
                    acc[j][v] *= (v < 2) ? corr0 : corr1;
            }
            m0 = mn0; m1 = mn1;

#pragma unroll
            for (int t = 0; t < 4; t++) {
                uint32_t pa[4];
                pa[0] = pack_h2(c[2 * t][0], c[2 * t][1]);
                pa[1] = pack_h2(c[2 * t][2], c[2 * t][3]);
                pa[2] = pack_h2(c[2 * t + 1][0], c[2 * t + 1][1]);
                pa[3] = pack_h2(c[2 * t + 1][2], c[2 * t + 1][3]);
#pragma unroll
                for (int nb = 0; nb < 4; nb++) {
                    uint32_t vb[4];
                    int key = t * 16 + ((lg & 1) << 3) + l7;
                    int chunk = nb * 2 + (lg >> 1);
                    uint32_t addr = sV + key * 128 + ((chunk ^ (key & 7)) << 4);
                    ldsm_x4_trans(vb[0], vb[1], vb[2], vb[3], addr);
                    mma_f16(acc[nb * 2],     pa, vb[0], vb[1]);
                    mma_f16(acc[nb * 2 + 1], pa, vb[2], vb[3]);
                }
            }
        }
        __syncthreads();
    }

    l0 += __shfl_xor_sync(0xffffffffu, l0, 1);
    l0 += __shfl_xor_sync(0xffffffffu, l0, 2);
    l1 += __shfl_xor_sync(0xffffffffu, l1, 1);
    l1 += __shfl_xor_sync(0xffffffffu, l1, 2);
    float inv0 = 1.f / l0, inv1 = 1.f / l1;
    int r0g = b * SEQ + qt * 128 + w * 16 + quad;
#pragma unroll
    for (int j = 0; j < 8; j++) {
        int col = h * 64 + j * 8 + tc2;
        *(uint32_t*)(z + (size_t)r0g * DM + col) = pack_h2(acc[j][0] * inv0, acc[j][1] * inv0);
        *(uint32_t*)(z + (size_t)(r0g + 8) * DM + col) =
            pack_h2(acc[j][2] * inv1, acc[j][3] * inv1);
    }
}

// ---------------- launch ----------------
extern "C" void kernel_launch(void* const* d_in, const int* in_sizes, int n_in,
                              void* d_out, int out_size) {
    const float* resid_pre = (const float*)d_in[0];
    const float* W_Q  = (const float*)d_in[1];
    const float* W_K  = (const float*)d_in[2];
    const float* W_V  = (const float*)d_in[3];
    const float* W_O  = (const float*)d_in[4];
    const float* b_Q  = (const float*)d_in[5];
    const float* b_K  = (const float*)d_in[6];
    const float* b_V  = (const float*)d_in[7];
    const float* b_O  = (const float*)d_in[8];
    const float* ln1w = (const float*)d_in[9];
    const float* ln1b = (const float*)d_in[10];
    const float* ln2w = (const float*)d_in[11];
    const float* ln2b = (const float*)d_in[12];
    const float* W_in  = (const float*)d_in[13];
    const float* b_in  = (const float*)d_in[14];
    const float* W_out = (const float*)d_in[15];
    const float* b_out = (const float*)d_in[16];
    float* out = (float*)d_out;

    __half *x16, *z16, *h16, *wqkv, *wo, *win, *wout;
    float *mid, *bqkv;
    cudaGetSymbolAddress((void**)&x16,  g_x16);
    cudaGetSymbolAddress((void**)&z16,  g_z16);
    cudaGetSymbolAddress((void**)&h16,  g_h16);
    cudaGetSymbolAddress((void**)&mid,  g_mid);
    cudaGetSymbolAddress((void**)&wqkv, g_wqkv);
    cudaGetSymbolAddress((void**)&wo,   g_wo);
    cudaGetSymbolAddress((void**)&win,  g_win);
    cudaGetSymbolAddress((void**)&wout, g_wout);
    cudaGetSymbolAddress((void**)&bqkv, g_bqkv);

    const int SMEM_G = 2 * STG_BYTES;           // 64KB, 2 CTA/SM
    const int SMEM_A = 16384 + 2 * 16384;       // 48KB attention
    cudaFuncSetAttribute(gemm_f16_kernel<1>, cudaFuncAttributeMaxDynamicSharedMemorySize, SMEM_G);
    cudaFuncSetAttribute(gemm_f16_kernel<2>, cudaFuncAttributeMaxDynamicSharedMemorySize, SMEM_G);
    cudaFuncSetAttribute(gemm_f16_kernel<3>, cudaFuncAttributeMaxDynamicSharedMemorySize, SMEM_G);
    cudaFuncSetAttribute(attn_kernel, cudaFuncAttributeMaxDynamicSharedMemorySize, SMEM_A);

    // weight packing (fp16, [N,K] layouts)
    pack_wqkv_kernel<<<(QKVN * DM + 255) / 256, 256>>>(W_Q, W_K, W_V, b_Q, b_K, b_V);
    transpose_pack_kernel<<<dim3(DM / 32, DM / 32),   dim3(32, 8)>>>(W_O,  wo,   DM,   DM);
    transpose_pack_kernel<<<dim3(DMLP / 32, DM / 32), dim3(32, 8)>>>(W_in, win,  DM,   DMLP);
    transpose_pack_kernel<<<dim3(DM / 32, DMLP / 32), dim3(32, 8)>>>(W_out, wout, DMLP, DM);

    // 1) LN1 -> fp16
    layernorm_kernel<<<ROWS, 256>>>(resid_pre, ln1w, ln1b, x16);
    // 2) fused QKV projection (fp16 mma) -> fp16 Q/K/V [b,h,s,d], Q in log2-softmax scale
    gemm_f16_kernel<3><<<dim3(QKVN / 128, ROWS / 128), 256, SMEM_G>>>(x16, wqkv, bqkv,
                                                                      nullptr, nullptr, QKVN, DM);
    // 3) tensor-core causal attention -> z (fp16)
    attn_kernel<<<dim3(SEQ / 128, NBH), 256, SMEM_A>>>(z16);
    // 4) O projection (fp16 mma) + bias + residual -> mid (fp32)
    gemm_f16_kernel<2><<<dim3(DM / 128, ROWS / 128), 256, SMEM_G>>>(z16, wo, b_O, resid_pre,
                                                                    mid, DM, DM);
    // 5) LN2 -> fp16
    layernorm_kernel<<<ROWS, 256>>>(mid, ln2w, ln2b, x16);
    // 6) MLP in + bias + GELU (fp16 mma) -> fp16 hidden
    gemm_f16_kernel<1><<<dim3(DMLP / 128, ROWS / 128), 256, SMEM_G>>>(x16, win, b_in, nullptr,
                                                                      h16, DMLP, DM);
    // 7) MLP out (fp16 mma) + bias + residual -> out (fp32)
    gemm_f16_kernel<2><<<dim3(DM / 128, ROWS / 128), 256, SMEM_G>>>(h16, wout, b_out, mid,
                                                                    out, DM, DMLP);
}